// round 14
// baseline (speedup 1.0000x reference)
#include <cuda_runtime.h>
#include <cuda_bf16.h>
#include <math.h>
#include <stdint.h>

// ---------------- problem constants ----------------
#define NN      16384
#define EE      131072
#define HH      256
#define LL      4
#define GB      256
#define NPG     64
#define NHEADS  8
#define DKH     32
#define DEG     8
#define FFD     512

// ---------------- fp32 scratch ----------------
__device__ float g_h[NN * HH];
__device__ float g_m[NN * HH];
__device__ float g_qkv[NN * 768];
__device__ float g_o[NN * HH];
__device__ float g_asd[2 * NN];     // [0]=alpha_src, [1]=alpha_dst
__device__ float g_gs[NN];
__device__ float g_wa[LL * 32];
__device__ float g_cb[LL];
__device__ float g_ce[LL * EE];

// ---------------- bf16 hi/lo scratch (activations) ----------------
__device__ __nv_bfloat16 g_nf_h[NN * 64],   g_nf_l[NN * 64];
__device__ __nv_bfloat16 g_h_h[NN * HH],    g_h_l[NN * HH];
__device__ __nv_bfloat16 g_ff_h[NN * FFD],  g_ff_l[NN * FFD];

// ---------------- bf16 hi/lo weights, transposed to [N][K] ----------------
__device__ __nv_bfloat16 g_wnt_h[HH * 64],        g_wnt_l[HH * 64];
__device__ __nv_bfloat16 g_gatwt_h[LL * HH * HH], g_gatwt_l[LL * HH * HH];
__device__ __nv_bfloat16 g_qkvt_h[768 * HH], g_qkvt_l[768 * HH];
__device__ __nv_bfloat16 g_ff1t_h[FFD * HH], g_ff1t_l[FFD * HH];
__device__ __nv_bfloat16 g_ff2t_h[HH * FFD], g_ff2t_l[HH * FFD];
__device__ __nv_bfloat16 g_gw1t_h[HH * HH],  g_gw1t_l[HH * HH];

// ================= conversion: fp32 -> (bf16 hi, lo), optional transpose =========
struct ConvEnt {
    const float* src;
    __nv_bfloat16* hi;
    __nv_bfloat16* lo;
    int K, N, trans, blk0, nblk;
};
struct ConvTab { ConvEnt e[13]; int n; };

__global__ __launch_bounds__(256) void conv_kernel(ConvTab tab)
{
    int b = blockIdx.x;
    int ei = 0;
    for (int i = 0; i < tab.n; i++)
        if (b >= tab.e[i].blk0) ei = i;
    ConvEnt e = tab.e[ei];
    int lb = b - e.blk0;
    int total = e.K * e.N;
    int base = lb * 1024;
#pragma unroll
    for (int j = 0; j < 4; j++) {
        int i = base + j * 256 + threadIdx.x;
        if (i < total) {
            float x = e.src[i];
            __nv_bfloat16 h = __float2bfloat16_rn(x);
            __nv_bfloat16 l = __float2bfloat16_rn(x - __bfloat162float(h));
            int di;
            if (e.trans) { int k = i / e.N, n = i % e.N; di = n * e.K + k; }
            else di = i;
            e.hi[di] = h;
            e.lo[di] = l;
        }
    }
}

// ================= pipelined tensor-core GEMM (R11 config, dual fused dots) ======
// BM=128, BN=128, BK=32, 2-stage cp.async (.ca), ldmatrix, 8 warps (2m x 4n),
// warp tile 64x32, 3 MMAs per fragment.
#define SA   40
#define BUFE (128 * SA)
#define SMEM_GEMM (8 * BUFE * 2)

__device__ __forceinline__ void mma_bf16(float* c, const uint32_t* a,
                                         uint32_t b0, uint32_t b1)
{
    asm volatile(
        "mma.sync.aligned.m16n8k16.row.col.f32.bf16.bf16.f32 "
        "{%0,%1,%2,%3}, {%4,%5,%6,%7}, {%8,%9}, {%0,%1,%2,%3};\n"
        : "+f"(c[0]), "+f"(c[1]), "+f"(c[2]), "+f"(c[3])
        : "r"(a[0]), "r"(a[1]), "r"(a[2]), "r"(a[3]), "r"(b0), "r"(b1));
}

__device__ __forceinline__ void cp16(void* s, const void* g)
{
    uint32_t sa = (uint32_t)__cvta_generic_to_shared(s);
    asm volatile("cp.async.ca.shared.global [%0], [%1], 16;\n" :: "r"(sa), "l"(g));
}

__device__ __forceinline__ void ldmat4(uint32_t& r0, uint32_t& r1,
                                       uint32_t& r2, uint32_t& r3, uint32_t addr)
{
    asm volatile("ldmatrix.sync.aligned.m8n8.x4.shared.b16 {%0,%1,%2,%3}, [%4];\n"
                 : "=r"(r0), "=r"(r1), "=r"(r2), "=r"(r3) : "r"(addr));
}

__global__ __launch_bounds__(256, 2) void gemm_tc(
    const __nv_bfloat16* __restrict__ Ah, const __nv_bfloat16* __restrict__ Al,
    const __nv_bfloat16* __restrict__ Bh, const __nv_bfloat16* __restrict__ Bl,
    const float* __restrict__ bias,
    float* __restrict__ Cf,
    __nv_bfloat16* __restrict__ Chi, __nv_bfloat16* __restrict__ Clo,
    const float* __restrict__ gvw,  float* __restrict__ gso,
    const float* __restrict__ gvw2, float* __restrict__ gso2,
    int M, int K, int Nout, int act)
{
    extern __shared__ __nv_bfloat16 sm[];
    __nv_bfloat16* sAh = sm;
    __nv_bfloat16* sAl = sm + 2 * BUFE;
    __nv_bfloat16* sBh = sm + 4 * BUFE;
    __nv_bfloat16* sBl = sm + 6 * BUFE;

    const int t = threadIdx.x;
    const int warp = t >> 5, lane = t & 31;
    const int wm = (warp & 1) * 64;
    const int wn = (warp >> 1) * 32;
    const int r = lane >> 2, c2 = (lane & 3) * 2;
    const int m0 = blockIdx.y * 128;
    const int n0 = blockIdx.x * 128;

    const int lr = t >> 2;
    const int lc = (t & 3) * 8;

    const int g8 = lane >> 3;
    const int lrow = (g8 & 1) * 8 + (lane & 7);
    const int kof = (g8 >> 1) * 8;

    float acc[4][4][4];
#pragma unroll
    for (int i = 0; i < 4; i++)
#pragma unroll
        for (int j = 0; j < 4; j++)
#pragma unroll
            for (int k = 0; k < 4; k++) acc[i][j][k] = 0.f;

    const __nv_bfloat16* pAh = Ah + (size_t)(m0 + lr) * K + lc;
    const __nv_bfloat16* pAl = Al + (size_t)(m0 + lr) * K + lc;
    const __nv_bfloat16* pBh = Bh + (size_t)(n0 + lr) * K + lc;
    const __nv_bfloat16* pBl = Bl + (size_t)(n0 + lr) * K + lc;
    const size_t rs64 = (size_t)64 * K;

    const int so0 = lr * SA + lc;
    const int so1 = (lr + 64) * SA + lc;

    uint32_t bAh = (uint32_t)__cvta_generic_to_shared(sAh);
    uint32_t bAl = (uint32_t)__cvta_generic_to_shared(sAl);
    uint32_t bBh = (uint32_t)__cvta_generic_to_shared(sBh);
    uint32_t bBl = (uint32_t)__cvta_generic_to_shared(sBl);

    uint32_t aoff[4], boff[2];
#pragma unroll
    for (int mt = 0; mt < 4; mt++)
        aoff[mt] = ((wm + mt * 16 + lrow) * SA + kof) * 2;
#pragma unroll
    for (int ntp = 0; ntp < 2; ntp++)
        boff[ntp] = ((wn + ntp * 16 + lrow) * SA + kof) * 2;

    cp16(&sAh[so0], pAh);            cp16(&sAh[so1], pAh + rs64);
    cp16(&sAl[so0], pAl);            cp16(&sAl[so1], pAl + rs64);
    cp16(&sBh[so0], pBh);            cp16(&sBh[so1], pBh + rs64);
    cp16(&sBl[so0], pBl);            cp16(&sBl[so1], pBl + rs64);
    asm volatile("cp.async.commit_group;\n");

    const int nIter = K >> 5;
    for (int i = 0; i < nIter; i++) {
        const int s = i & 1;
        if (i + 1 < nIter) {
            int k0 = (i + 1) << 5;
            int nso = ((i + 1) & 1) * BUFE;
            cp16(&sAh[nso + so0], pAh + k0);  cp16(&sAh[nso + so1], pAh + rs64 + k0);
            cp16(&sAl[nso + so0], pAl + k0);  cp16(&sAl[nso + so1], pAl + rs64 + k0);
            cp16(&sBh[nso + so0], pBh + k0);  cp16(&sBh[nso + so1], pBh + rs64 + k0);
            cp16(&sBl[nso + so0], pBl + k0);  cp16(&sBl[nso + so1], pBl + rs64 + k0);
            asm volatile("cp.async.commit_group;\n");
            asm volatile("cp.async.wait_group 1;\n");
        } else {
            asm volatile("cp.async.wait_group 0;\n");
        }
        __syncthreads();

        const uint32_t sb = s * BUFE * 2;
#pragma unroll
        for (int ks = 0; ks < 2; ks++) {
            const uint32_t kso = sb + ks * 32;
            uint32_t ah[4][4], al[4][4];
#pragma unroll
            for (int mt = 0; mt < 4; mt++) {
                ldmat4(ah[mt][0], ah[mt][1], ah[mt][2], ah[mt][3], bAh + kso + aoff[mt]);
                ldmat4(al[mt][0], al[mt][1], al[mt][2], al[mt][3], bAl + kso + aoff[mt]);
            }
#pragma unroll
            for (int ntp = 0; ntp < 2; ntp++) {
                uint32_t h0, h1, h2, h3, l0, l1, l2, l3;
                ldmat4(h0, h1, h2, h3, bBh + kso + boff[ntp]);
                ldmat4(l0, l1, l2, l3, bBl + kso + boff[ntp]);
#pragma unroll
                for (int mt = 0; mt < 4; mt++) {
                    mma_bf16(acc[mt][2 * ntp],     ah[mt], h0, h2);
                    mma_bf16(acc[mt][2 * ntp],     al[mt], h0, h2);
                    mma_bf16(acc[mt][2 * ntp],     ah[mt], l0, l2);
                    mma_bf16(acc[mt][2 * ntp + 1], ah[mt], h1, h3);
                    mma_bf16(acc[mt][2 * ntp + 1], al[mt], h1, h3);
                    mma_bf16(acc[mt][2 * ntp + 1], ah[mt], l1, l3);
                }
            }
        }
        __syncthreads();
    }

    // epilogue (+ optional fused row-dot pairs) — rowaccs initialized here so
    // their liveness does not overlap the mainloop register peak.
    float rowacc[4][2], rowacc2[4][2];
#pragma unroll
    for (int i = 0; i < 4; i++) {
        rowacc[i][0] = 0.f;  rowacc[i][1] = 0.f;
        rowacc2[i][0] = 0.f; rowacc2[i][1] = 0.f;
    }

#pragma unroll
    for (int nt = 0; nt < 4; nt++) {
        int col = n0 + wn + nt * 8 + c2;
        float b0 = bias ? bias[col] : 0.f;
        float b1 = bias ? bias[col + 1] : 0.f;
        float w0 = gvw ? gvw[col] : 0.f;
        float w1 = gvw ? gvw[col + 1] : 0.f;
        float u0 = gvw2 ? gvw2[col] : 0.f;
        float u1 = gvw2 ? gvw2[col + 1] : 0.f;
#pragma unroll
        for (int mt = 0; mt < 4; mt++) {
            int row = m0 + wm + mt * 16 + r;
#pragma unroll
            for (int half = 0; half < 2; half++) {
                int rr = row + half * 8;
                float v0 = acc[mt][nt][half * 2 + 0] + b0;
                float v1 = acc[mt][nt][half * 2 + 1] + b1;
                if (act == 1) { v0 = fmaxf(v0, 0.f); v1 = fmaxf(v1, 0.f); }
                else if (act == 2) {
                    v0 = 0.5f * v0 * (1.f + erff(v0 * 0.70710678118654752f));
                    v1 = 0.5f * v1 * (1.f + erff(v1 * 0.70710678118654752f));
                }
                if (gvw)  rowacc[mt][half]  += v0 * w0 + v1 * w1;
                if (gvw2) rowacc2[mt][half] += v0 * u0 + v1 * u1;
                size_t o = (size_t)rr * Nout + col;
                if (Cf) *(float2*)(Cf + o) = make_float2(v0, v1);
                if (Chi) {
                    __nv_bfloat16 h0 = __float2bfloat16_rn(v0);
                    __nv_bfloat16 h1 = __float2bfloat16_rn(v1);
                    __nv_bfloat162 hp; hp.x = h0; hp.y = h1;
                    *(__nv_bfloat162*)(Chi + o) = hp;
                    __nv_bfloat162 lp;
                    lp.x = __float2bfloat16_rn(v0 - __bfloat162float(h0));
                    lp.y = __float2bfloat16_rn(v1 - __bfloat162float(h1));
                    *(__nv_bfloat162*)(Clo + o) = lp;
                }
            }
        }
    }
    if (gvw) {
#pragma unroll
        for (int mt = 0; mt < 4; mt++)
#pragma unroll
            for (int half = 0; half < 2; half++) {
                float v = rowacc[mt][half];
                v += __shfl_xor_sync(0xffffffffu, v, 1);
                v += __shfl_xor_sync(0xffffffffu, v, 2);
                float u = rowacc2[mt][half];
                u += __shfl_xor_sync(0xffffffffu, u, 1);
                u += __shfl_xor_sync(0xffffffffu, u, 2);
                if ((lane & 3) == 0) {
                    int row = m0 + wm + mt * 16 + r + half * 8;
                    atomicAdd(gso + row, v);
                    if (gvw2) atomicAdd(gso2 + row, u);
                }
            }
    }
}

// ---------------- fold edge projection into per-layer 32-dim vector ----------------
__global__ void wa_kernel(const float* __restrict__ We, const float* __restrict__ be,
                          const float* __restrict__ gat_a)
{
    int l = blockIdx.x;
    int t = threadIdx.x;
    const float* a = gat_a + l * (3 * HH) + 2 * HH;
    if (t < 32) {
        float s = 0.f;
        const float* row = We + t * HH;
        for (int j = 0; j < HH; j++) s += row[j] * a[j];
        g_wa[l * 32 + t] = s;
    } else if (t == 32) {
        float s = 0.f;
        for (int j = 0; j < HH; j++) s += be[j] * a[j];
        g_cb[l] = s;
    }
}

// ---------------- per-edge ce for ALL layers ----------------
__global__ __launch_bounds__(256) void ce_kernel(const float* __restrict__ ef)
{
    int e = blockIdx.x * 256 + threadIdx.x;
    float4 v[8];
    const float4* row = (const float4*)(ef + (size_t)e * 32);
#pragma unroll
    for (int i = 0; i < 8; i++) v[i] = row[i];
#pragma unroll
    for (int l = 0; l < LL; l++) {
        const float* wa = g_wa + l * 32;
        float s = g_cb[l];
#pragma unroll
        for (int i = 0; i < 8; i++) {
            s += v[i].x * wa[4 * i + 0];
            s += v[i].y * wa[4 * i + 1];
            s += v[i].z * wa[4 * i + 2];
            s += v[i].w * wa[4 * i + 3];
        }
        g_ce[l * EE + e] = s;
    }
}

// ---------------- graph-resident GAT layer (512 threads, alpha from gemm) -------
#define GATSM (NPG * HH * 4 + (64 + 64 + 512) * 4 + 512 * 4)

__global__ __launch_bounds__(512) void gat_layer_kernel(
    const int* __restrict__ dst, const float* __restrict__ ce_l,
    const float* __restrict__ lng, const float* __restrict__ lnb, int l)
{
    extern __shared__ float smf[];
    float* smm = smf;
    float* sas = smf + NPG * HH;
    float* sad = sas + 64;
    float* swt = sad + 64;
    int*   sdl = (int*)(swt + 512);

    const int g = blockIdx.x;
    const int t = threadIdx.x;
    const int warp = t >> 5, lane = t & 31;

    // load m tile + alpha vectors (computed by the GEMM epilogue)
    {
        const float4* src = (const float4*)(g_m + (size_t)g * NPG * HH);
        float4* dstp = (float4*)smm;
#pragma unroll
        for (int i = 0; i < 8; i++)
            dstp[t + 512 * i] = src[t + 512 * i];
        if (t < NPG) {
            sas[t] = g_asd[g * NPG + t];
            sad[t] = g_asd[NN + g * NPG + t];
        }
    }
    __syncthreads();

    if (t < NPG) {
        float lg[DEG];
        int   dl[DEG];
#pragma unroll
        for (int k = 0; k < DEG; k++) {
            int e = t * DEG + k;
            int d = dst[g * (NPG * DEG) + e] - g * NPG;
            dl[k] = d;
            float x = sas[t] + sad[d] + ce_l[g * (NPG * DEG) + e];
            lg[k] = (x >= 0.f) ? x : 0.01f * x;
        }
        float mx = -1e30f;
#pragma unroll
        for (int k = 0; k < DEG; k++) mx = fmaxf(mx, lg[k]);
        float ws = 0.f;
#pragma unroll
        for (int k = 0; k < DEG; k++) { lg[k] = __expf(lg[k] - mx); ws += lg[k]; }
        float inv = 1.f / ws;
#pragma unroll
        for (int k = 0; k < DEG; k++) {
            swt[t * DEG + k] = lg[k] * inv;
            sdl[t * DEG + k] = dl[k];
        }
        // re-zero alpha accumulators for the next layer's GEMM
        g_asd[g * NPG + t] = 0.f;
        g_asd[NN + g * NPG + t] = 0.f;
    }
    __syncthreads();

#pragma unroll
    for (int q = 0; q < 4; q++) {
        int i = warp * 4 + q;
        float acc[8] = {0.f, 0.f, 0.f, 0.f, 0.f, 0.f, 0.f, 0.f};
#pragma unroll
        for (int k = 0; k < DEG; k++) {
            float wk = swt[i * DEG + k];
            const float4* mr = (const float4*)(smm + sdl[i * DEG + k] * HH) + lane * 2;
            float4 v0 = mr[0], v1 = mr[1];
            acc[0] += wk * v0.x; acc[1] += wk * v0.y;
            acc[2] += wk * v0.z; acc[3] += wk * v0.w;
            acc[4] += wk * v1.x; acc[5] += wk * v1.y;
            acc[6] += wk * v1.z; acc[7] += wk * v1.w;
        }
        size_t rowo = (size_t)(g * NPG + i) * HH + lane * 8;
        const float4* hr = (const float4*)(g_h + rowo);
        float4 h0 = hr[0], h1 = hr[1];
        float x[8];
        x[0] = acc[0] + h0.x; x[1] = acc[1] + h0.y;
        x[2] = acc[2] + h0.z; x[3] = acc[3] + h0.w;
        x[4] = acc[4] + h1.x; x[5] = acc[5] + h1.y;
        x[6] = acc[6] + h1.z; x[7] = acc[7] + h1.w;

        float s = 0.f, s2 = 0.f;
#pragma unroll
        for (int c = 0; c < 8; c++) { s += x[c]; s2 += x[c] * x[c]; }
#pragma unroll
        for (int off = 16; off; off >>= 1) {
            s  += __shfl_xor_sync(0xffffffffu, s,  off);
            s2 += __shfl_xor_sync(0xffffffffu, s2, off);
        }
        float mean = s * (1.f / HH);
        float var  = s2 * (1.f / HH) - mean * mean;
        float rstd = rsqrtf(var + 1e-5f);

        const float4* gg = (const float4*)(lng + l * HH + lane * 8);
        const float4* bb = (const float4*)(lnb + l * HH + lane * 8);
        float4 gv0 = gg[0], gv1 = gg[1];
        float4 bv0 = bb[0], bv1 = bb[1];
        float y[8];
        y[0] = (x[0] - mean) * rstd * gv0.x + bv0.x;
        y[1] = (x[1] - mean) * rstd * gv0.y + bv0.y;
        y[2] = (x[2] - mean) * rstd * gv0.z + bv0.z;
        y[3] = (x[3] - mean) * rstd * gv0.w + bv0.w;
        y[4] = (x[4] - mean) * rstd * gv1.x + bv1.x;
        y[5] = (x[5] - mean) * rstd * gv1.y + bv1.y;
        y[6] = (x[6] - mean) * rstd * gv1.z + bv1.z;
        y[7] = (x[7] - mean) * rstd * gv1.w + bv1.w;

        float4* ho = (float4*)(g_h + rowo);
        ho[0] = make_float4(y[0], y[1], y[2], y[3]);
        ho[1] = make_float4(y[4], y[5], y[6], y[7]);

        uint32_t hi[4], lo[4];
#pragma unroll
        for (int c = 0; c < 4; c++) {
            __nv_bfloat16 a0 = __float2bfloat16_rn(y[2 * c]);
            __nv_bfloat16 a1 = __float2bfloat16_rn(y[2 * c + 1]);
            __nv_bfloat162 hp; hp.x = a0; hp.y = a1;
            hi[c] = *(uint32_t*)&hp;
            __nv_bfloat162 lp;
            lp.x = __float2bfloat16_rn(y[2 * c] - __bfloat162float(a0));
            lp.y = __float2bfloat16_rn(y[2 * c + 1] - __bfloat162float(a1));
            lo[c] = *(uint32_t*)&lp;
        }
        *(uint4*)(g_h_h + rowo) = make_uint4(hi[0], hi[1], hi[2], hi[3]);
        *(uint4*)(g_h_l + rowo) = make_uint4(lo[0], lo[1], lo[2], lo[3]);
    }
}

// ---------------- residual + LayerNorm (+ optional bf16 hi/lo out) ----------------
__global__ __launch_bounds__(256) void ln_kernel(
    const float* __restrict__ xa, const float* __restrict__ xb,
    const float* __restrict__ g, const float* __restrict__ b,
    float* __restrict__ out,
    __nv_bfloat16* __restrict__ ohi, __nv_bfloat16* __restrict__ olo,
    float eps)
{
    __shared__ float rs[8], rs2[8];
    int n = blockIdx.x;
    int t = threadIdx.x;
    int warp = t >> 5, lane = t & 31;
    float x = xa[(size_t)n * HH + t] + xb[(size_t)n * HH + t];
    float s = x, s2 = x * x;
#pragma unroll
    for (int off = 16; off; off >>= 1) {
        s  += __shfl_xor_sync(0xffffffffu, s,  off);
        s2 += __shfl_xor_sync(0xffffffffu, s2, off);
    }
    if (lane == 0) { rs[warp] = s; rs2[warp] = s2; }
    __syncthreads();
    if (warp == 0) {
        float a = (lane < 8) ? rs[lane]  : 0.f;
        float c = (lane < 8) ? rs2[lane] : 0.f;
#pragma unroll
        for (int off = 4; off; off >>= 1) {
            a += __shfl_xor_sync(0xffffffffu, a, off);
            c += __shfl_xor_sync(0xffffffffu, c, off);
        }
        if (lane == 0) { rs[0] = a; rs2[0] = c; }
    }
    __syncthreads();
    float mean = rs[0] * (1.f / HH);
    float var  = rs2[0] * (1.f / HH) - mean * mean;
    float y = (x - mean) * rsqrtf(var + eps) * g[t] + b[t];
    size_t o = (size_t)n * HH + t;
    out[o] = y;
    if (ohi) {
        __nv_bfloat16 hh = __float2bfloat16_rn(y);
        ohi[o] = hh;
        olo[o] = __float2bfloat16_rn(y - __bfloat162float(hh));
    }
}

// ---------------- per-(graph, head) global attention (packed qkv) ----------------
__global__ __launch_bounds__(256) void attn_kernel()
{
    __shared__ float qs[NPG][33];
    __shared__ float ks[NPG][33];
    __shared__ float vs[NPG][DKH];
    __shared__ float pb[8][NPG];

    int head = blockIdx.x;
    int b = blockIdx.y;
    int t = threadIdx.x;
    int warp = t >> 5, lane = t & 31;

    for (int idx = t; idx < NPG * DKH; idx += 256) {
        int r = idx >> 5, d = idx & 31;
        size_t g = (size_t)(b * NPG + r) * 768 + head * DKH + d;
        qs[r][d] = g_qkv[g];
        ks[r][d] = g_qkv[g + 256];
        vs[r][d] = g_qkv[g + 512];
    }
    __syncthreads();

    const float scale = 0.17677669529663687f;
    for (int r = 0; r < 8; r++) {
        int i = warp * 8 + r;
        float s0 = 0.f, s1 = 0.f;
#pragma unroll
        for (int d = 0; d < DKH; d++) {
            float qd = qs[i][d];
            s0 += qd * ks[lane][d];
            s1 += qd * ks[lane + 32][d];
        }
        s0 *= scale; s1 *= scale;
        float mx = fmaxf(s0, s1);
#pragma unroll
        for (int off = 16; off; off >>= 1)
            mx = fmaxf(mx, __shfl_xor_sync(0xffffffffu, mx, off));
        float e0 = __expf(s0 - mx), e1 = __expf(s1 - mx);
        float sm = e0 + e1;
#pragma unroll
        for (int off = 16; off; off >>= 1)
            sm += __shfl_xor_sync(0xffffffffu, sm, off);
        float inv = 1.f / sm;
        pb[warp][lane] = e0 * inv;
        pb[warp][lane + 32] = e1 * inv;
        __syncwarp();
        float o = 0.f;
#pragma unroll
        for (int j = 0; j < NPG; j++) o += pb[warp][j] * vs[j][lane];
        g_o[(size_t)(b * NPG + i) * HH + head * DKH + lane] = o;
    }
}

// ---------------- gated readout per graph ----------------
__global__ __launch_bounds__(256) void readout_kernel(float* __restrict__ out)
{
    __shared__ float p[NPG];
    int b = blockIdx.x;
    int t = threadIdx.x;
    if (t < NPG) p[t] = g_gs[b * NPG + t];
    __syncthreads();
    float mx = -1e30f;
#pragma unroll
    for (int i = 0; i < NPG; i++) mx = fmaxf(mx, p[i]);
    float s = 0.f, acc = 0.f;
    for (int i = 0; i < NPG; i++) {
        float w = __expf(p[i] - mx);
        s += w;
        acc += w * g_h[(size_t)(b * NPG + i) * HH + t];
    }
    out[b * HH + t] = acc / s;
}

// ---------------- host launcher ----------------
static inline __nv_bfloat16* sym(const void* s)
{
    void* p = nullptr;
    cudaGetSymbolAddress(&p, s);
    return (__nv_bfloat16*)p;
}

extern "C" void kernel_launch(void* const* d_in, const int* in_sizes, int n_in,
                              void* d_out, int out_size)
{
    const float* node_feats = (const float*)d_in[0];
    const float* edge_feats = (const float*)d_in[1];
    const int*   dst        = (const int*)  d_in[3];
    const float* Wn   = (const float*)d_in[4];
    const float* bn   = (const float*)d_in[5];
    const float* We   = (const float*)d_in[6];
    const float* be   = (const float*)d_in[7];
    const float* gatW = (const float*)d_in[8];
    const float* gata = (const float*)d_in[9];
    const float* glng = (const float*)d_in[10];
    const float* glnb = (const float*)d_in[11];
    const float* Wq   = (const float*)d_in[12];
    const float* Wk   = (const float*)d_in[13];
    const float* Wv   = (const float*)d_in[14];
    const float* alng = (const float*)d_in[15];
    const float* alnb = (const float*)d_in[16];
    const float* fW1  = (const float*)d_in[17];
    const float* fb1  = (const float*)d_in[18];
    const float* fW2  = (const float*)d_in[19];
    const float* fb2  = (const float*)d_in[20];
    const float* flng = (const float*)d_in[21];
    const float* flnb = (const float*)d_in[22];
    const float* gW1  = (const float*)d_in[23];
    const float* gb1  = (const float*)d_in[24];
    const float* gW2  = (const float*)d_in[25];
    float* out = (float*)d_out;

    cudaFuncSetAttribute(gemm_tc, cudaFuncAttributeMaxDynamicSharedMemorySize,
                         SMEM_GEMM);
    cudaFuncSetAttribute(gat_layer_kernel,
                         cudaFuncAttributeMaxDynamicSharedMemorySize, GATSM);

    float *h_p, *m_p, *qkv_p, *o_p, *ce_p, *gs_p, *asd_p;
    cudaGetSymbolAddress((void**)&h_p, g_h);
    cudaGetSymbolAddress((void**)&m_p, g_m);
    cudaGetSymbolAddress((void**)&qkv_p, g_qkv);
    cudaGetSymbolAddress((void**)&o_p, g_o);
    cudaGetSymbolAddress((void**)&ce_p, g_ce);
    cudaGetSymbolAddress((void**)&gs_p, g_gs);
    cudaGetSymbolAddress((void**)&asd_p, g_asd);

    __nv_bfloat16 *nf_h = sym(g_nf_h), *nf_l = sym(g_nf_l);
    __nv_bfloat16 *h_h = sym(g_h_h),  *h_l = sym(g_h_l);
    __nv_bfloat16 *ff_h = sym(g_ff_h), *ff_l = sym(g_ff_l);
    __nv_bfloat16 *wnt_h = sym(g_wnt_h), *wnt_l = sym(g_wnt_l);
    __nv_bfloat16 *gwt_h = sym(g_gatwt_h), *gwt_l = sym(g_gatwt_l);
    __nv_bfloat16 *qkvt_h = sym(g_qkvt_h), *qkvt_l = sym(g_qkvt_l);
    __nv_bfloat16 *f1t_h = sym(g_ff1t_h), *f1t_l = sym(g_ff1t_l);
    __nv_bfloat16 *f2t_h = sym(g_ff2t_h), *f2t_l = sym(g_ff2t_l);
    __nv_bfloat16 *g1t_h = sym(g_gw1t_h), *g1t_l = sym(g_gw1t_l);

    ConvTab tab;
    int ne = 0, blk = 0;
    auto add = [&](const float* s, __nv_bfloat16* hi, __nv_bfloat16* lo,
                   int K, int N, int tr) {
        int nb = (K * N + 1023) / 1024;
        tab.e[ne] = {s, hi, lo, K, N, tr, blk, nb};
        blk += nb; ne++;
    };
    add(Wn, wnt_h, wnt_l, 64, HH, 1);
    for (int l = 0; l < LL; l++)
        add(gatW + (size_t)l * HH * HH, gwt_h + (size_t)l * HH * HH,
            gwt_l + (size_t)l * HH * HH, HH, HH, 1);
    add(Wq, qkvt_h, qkvt_l, HH, HH, 1);
    add(Wk, qkvt_h + 256 * HH, qkvt_l + 256 * HH, HH, HH, 1);
    add(Wv, qkvt_h + 512 * HH, qkvt_l + 512 * HH, HH, HH, 1);
    add(fW1, f1t_h, f1t_l, HH, FFD, 1);
    add(fW2, f2t_h, f2t_l, FFD, HH, 1);
    add(gW1, g1t_h, g1t_l, HH, HH, 1);
    add(node_feats, nf_h, nf_l, NN, 64, 0);
    tab.n = ne;

    conv_kernel<<<blk, 256>>>(tab);
    wa_kernel<<<LL, 64>>>(We, be, gata);
    ce_kernel<<<EE / 256, 256>>>(edge_feats);
    cudaMemsetAsync(gs_p, 0, NN * sizeof(float));
    cudaMemsetAsync(asd_p, 0, 2 * NN * sizeof(float));

    dim3 gH(HH / 128, NN / 128);     // (2, 128)
    dim3 gQKV(768 / 128, NN / 128);  // (6, 128)
    dim3 gF(FFD / 128, NN / 128);    // (4, 128)

    gemm_tc<<<gH, 256, SMEM_GEMM>>>(nf_h, nf_l, wnt_h, wnt_l, bn, h_p, h_h, h_l,
                                    nullptr, nullptr, nullptr, nullptr,
                                    NN, 64, HH, 0);

    for (int l = 0; l < LL; l++) {
        // GAT projection + fused alpha dots (as = m@a1, ad = m@a2)
        const float* a1 = gata + (size_t)l * 3 * HH;
        gemm_tc<<<gH, 256, SMEM_GEMM>>>(h_h, h_l, gwt_h + (size_t)l * HH * HH,
                                        gwt_l + (size_t)l * HH * HH, nullptr,
                                        m_p, nullptr, nullptr,
                                        a1, asd_p, a1 + HH, asd_p + NN,
                                        NN, HH, HH, 0);
        gat_layer_kernel<<<GB, 512, GATSM>>>(dst, ce_p + (size_t)l * EE,
                                             glng, glnb, l);
    }

    gemm_tc<<<gQKV, 256, SMEM_GEMM>>>(h_h, h_l, qkvt_h, qkvt_l, nullptr, qkv_p,
                                      nullptr, nullptr, nullptr, nullptr,
                                      nullptr, nullptr, NN, HH, 768, 0);
    attn_kernel<<<dim3(NHEADS, GB), 256>>>();
    ln_kernel<<<NN, 256>>>(o_p, h_p, alng, alnb, h_p, h_h, h_l, 1e-6f);

    gemm_tc<<<gF, 256, SMEM_GEMM>>>(h_h, h_l, f1t_h, f1t_l, fb1, nullptr,
                                    ff_h, ff_l, nullptr, nullptr,
                                    nullptr, nullptr, NN, HH, FFD, 2);
    gemm_tc<<<gH, 256, SMEM_GEMM>>>(ff_h, ff_l, f2t_h, f2t_l, fb2, m_p,
                                    nullptr, nullptr, nullptr, nullptr,
                                    nullptr, nullptr, NN, FFD, HH, 0);
    ln_kernel<<<NN, 256>>>(h_p, m_p, flng, flnb, h_p, h_h, h_l, 1e-6f);

    // gating: relu(x@gW1+gb1) fused with dot(gW2) into g_gs (atomic epilogue)
    gemm_tc<<<gH, 256, SMEM_GEMM>>>(h_h, h_l, g1t_h, g1t_l, gb1, nullptr,
                                    nullptr, nullptr, gW2, gs_p,
                                    nullptr, nullptr, NN, HH, HH, 1);
    readout_kernel<<<GB, 256>>>(out);

    (void)in_sizes; (void)n_in; (void)out_size;
}

// round 15
// speedup vs baseline: 1.5529x; 1.5529x over previous
#include <cuda_runtime.h>
#include <cuda_bf16.h>
#include <math.h>
#include <stdint.h>

// ---------------- problem constants ----------------
#define NN      16384
#define EE      131072
#define HH      256
#define LL      4
#define GB      256
#define NPG     64
#define NHEADS  8
#define DKH     32
#define DEG     8
#define FFD     512

// ---------------- fp32 scratch ----------------
__device__ float g_h[NN * HH];
__device__ float g_m[NN * HH];
__device__ float g_qkv[NN * 768];
__device__ float g_o[NN * HH];
__device__ float g_gs[NN];
__device__ float g_wa[LL * 32];
__device__ float g_cb[LL];
__device__ float g_ce[LL * EE];

// ---------------- bf16 hi/lo scratch (activations) ----------------
__device__ __nv_bfloat16 g_nf_h[NN * 64],   g_nf_l[NN * 64];
__device__ __nv_bfloat16 g_h_h[NN * HH],    g_h_l[NN * HH];
__device__ __nv_bfloat16 g_ff_h[NN * FFD],  g_ff_l[NN * FFD];

// ---------------- bf16 hi/lo weights, transposed to [N][K] ----------------
__device__ __nv_bfloat16 g_wnt_h[HH * 64],        g_wnt_l[HH * 64];
__device__ __nv_bfloat16 g_gatwt_h[LL * HH * HH], g_gatwt_l[LL * HH * HH];
__device__ __nv_bfloat16 g_qkvt_h[768 * HH], g_qkvt_l[768 * HH];
__device__ __nv_bfloat16 g_ff1t_h[FFD * HH], g_ff1t_l[FFD * HH];
__device__ __nv_bfloat16 g_ff2t_h[HH * FFD], g_ff2t_l[HH * FFD];
__device__ __nv_bfloat16 g_gw1t_h[HH * HH],  g_gw1t_l[HH * HH];

// ================= conversion: fp32 -> (bf16 hi, lo), optional transpose =========
struct ConvEnt {
    const float* src;
    __nv_bfloat16* hi;
    __nv_bfloat16* lo;
    int K, N, trans, blk0, nblk;
};
struct ConvTab { ConvEnt e[13]; int n; };

__global__ __launch_bounds__(256) void conv_kernel(ConvTab tab)
{
    int b = blockIdx.x;
    int ei = 0;
    for (int i = 0; i < tab.n; i++)
        if (b >= tab.e[i].blk0) ei = i;
    ConvEnt e = tab.e[ei];
    int lb = b - e.blk0;
    int total = e.K * e.N;
    int base = lb * 1024;
#pragma unroll
    for (int j = 0; j < 4; j++) {
        int i = base + j * 256 + threadIdx.x;
        if (i < total) {
            float x = e.src[i];
            __nv_bfloat16 h = __float2bfloat16_rn(x);
            __nv_bfloat16 l = __float2bfloat16_rn(x - __bfloat162float(h));
            int di;
            if (e.trans) { int k = i / e.N, n = i % e.N; di = n * e.K + k; }
            else di = i;
            e.hi[di] = h;
            e.lo[di] = l;
        }
    }
}

// ================= pipelined tensor-core GEMM (R7/R11 config + fused gate) ======
#define SA   40
#define BUFE (128 * SA)
#define SMEM_GEMM (8 * BUFE * 2)

__device__ __forceinline__ void mma_bf16(float* c, const uint32_t* a,
                                         uint32_t b0, uint32_t b1)
{
    asm volatile(
        "mma.sync.aligned.m16n8k16.row.col.f32.bf16.bf16.f32 "
        "{%0,%1,%2,%3}, {%4,%5,%6,%7}, {%8,%9}, {%0,%1,%2,%3};\n"
        : "+f"(c[0]), "+f"(c[1]), "+f"(c[2]), "+f"(c[3])
        : "r"(a[0]), "r"(a[1]), "r"(a[2]), "r"(a[3]), "r"(b0), "r"(b1));
}

__device__ __forceinline__ void cp16(void* s, const void* g)
{
    uint32_t sa = (uint32_t)__cvta_generic_to_shared(s);
    asm volatile("cp.async.ca.shared.global [%0], [%1], 16;\n" :: "r"(sa), "l"(g));
}

__device__ __forceinline__ void ldmat4(uint32_t& r0, uint32_t& r1,
                                       uint32_t& r2, uint32_t& r3, uint32_t addr)
{
    asm volatile("ldmatrix.sync.aligned.m8n8.x4.shared.b16 {%0,%1,%2,%3}, [%4];\n"
                 : "=r"(r0), "=r"(r1), "=r"(r2), "=r"(r3) : "r"(addr));
}

__global__ __launch_bounds__(256, 2) void gemm_tc(
    const __nv_bfloat16* __restrict__ Ah, const __nv_bfloat16* __restrict__ Al,
    const __nv_bfloat16* __restrict__ Bh, const __nv_bfloat16* __restrict__ Bl,
    const float* __restrict__ bias,
    float* __restrict__ Cf,
    __nv_bfloat16* __restrict__ Chi, __nv_bfloat16* __restrict__ Clo,
    const float* __restrict__ gvw, float* __restrict__ gso,
    int M, int K, int Nout, int act)
{
    extern __shared__ __nv_bfloat16 sm[];
    __nv_bfloat16* sAh = sm;
    __nv_bfloat16* sAl = sm + 2 * BUFE;
    __nv_bfloat16* sBh = sm + 4 * BUFE;
    __nv_bfloat16* sBl = sm + 6 * BUFE;

    const int t = threadIdx.x;
    const int warp = t >> 5, lane = t & 31;
    const int wm = (warp & 1) * 64;
    const int wn = (warp >> 1) * 32;
    const int r = lane >> 2, c2 = (lane & 3) * 2;
    const int m0 = blockIdx.y * 128;
    const int n0 = blockIdx.x * 128;

    const int lr = t >> 2;
    const int lc = (t & 3) * 8;

    const int g8 = lane >> 3;
    const int lrow = (g8 & 1) * 8 + (lane & 7);
    const int kof = (g8 >> 1) * 8;

    float acc[4][4][4];
#pragma unroll
    for (int i = 0; i < 4; i++)
#pragma unroll
        for (int j = 0; j < 4; j++)
#pragma unroll
            for (int k = 0; k < 4; k++) acc[i][j][k] = 0.f;

    const __nv_bfloat16* pAh = Ah + (size_t)(m0 + lr) * K + lc;
    const __nv_bfloat16* pAl = Al + (size_t)(m0 + lr) * K + lc;
    const __nv_bfloat16* pBh = Bh + (size_t)(n0 + lr) * K + lc;
    const __nv_bfloat16* pBl = Bl + (size_t)(n0 + lr) * K + lc;
    const size_t rs64 = (size_t)64 * K;

    const int so0 = lr * SA + lc;
    const int so1 = (lr + 64) * SA + lc;

    uint32_t bAh = (uint32_t)__cvta_generic_to_shared(sAh);
    uint32_t bAl = (uint32_t)__cvta_generic_to_shared(sAl);
    uint32_t bBh = (uint32_t)__cvta_generic_to_shared(sBh);
    uint32_t bBl = (uint32_t)__cvta_generic_to_shared(sBl);

    uint32_t aoff[4], boff[2];
#pragma unroll
    for (int mt = 0; mt < 4; mt++)
        aoff[mt] = ((wm + mt * 16 + lrow) * SA + kof) * 2;
#pragma unroll
    for (int ntp = 0; ntp < 2; ntp++)
        boff[ntp] = ((wn + ntp * 16 + lrow) * SA + kof) * 2;

    cp16(&sAh[so0], pAh);            cp16(&sAh[so1], pAh + rs64);
    cp16(&sAl[so0], pAl);            cp16(&sAl[so1], pAl + rs64);
    cp16(&sBh[so0], pBh);            cp16(&sBh[so1], pBh + rs64);
    cp16(&sBl[so0], pBl);            cp16(&sBl[so1], pBl + rs64);
    asm volatile("cp.async.commit_group;\n");

    const int nIter = K >> 5;
    for (int i = 0; i < nIter; i++) {
        const int s = i & 1;
        if (i + 1 < nIter) {
            int k0 = (i + 1) << 5;
            int nso = ((i + 1) & 1) * BUFE;
            cp16(&sAh[nso + so0], pAh + k0);  cp16(&sAh[nso + so1], pAh + rs64 + k0);
            cp16(&sAl[nso + so0], pAl + k0);  cp16(&sAl[nso + so1], pAl + rs64 + k0);
            cp16(&sBh[nso + so0], pBh + k0);  cp16(&sBh[nso + so1], pBh + rs64 + k0);
            cp16(&sBl[nso + so0], pBl + k0);  cp16(&sBl[nso + so1], pBl + rs64 + k0);
            asm volatile("cp.async.commit_group;\n");
            asm volatile("cp.async.wait_group 1;\n");
        } else {
            asm volatile("cp.async.wait_group 0;\n");
        }
        __syncthreads();

        const uint32_t sb = s * BUFE * 2;
#pragma unroll
        for (int ks = 0; ks < 2; ks++) {
            const uint32_t kso = sb + ks * 32;
            uint32_t ah[4][4], al[4][4];
#pragma unroll
            for (int mt = 0; mt < 4; mt++) {
                ldmat4(ah[mt][0], ah[mt][1], ah[mt][2], ah[mt][3], bAh + kso + aoff[mt]);
                ldmat4(al[mt][0], al[mt][1], al[mt][2], al[mt][3], bAl + kso + aoff[mt]);
            }
#pragma unroll
            for (int ntp = 0; ntp < 2; ntp++) {
                uint32_t h0, h1, h2, h3, l0, l1, l2, l3;
                ldmat4(h0, h1, h2, h3, bBh + kso + boff[ntp]);
                ldmat4(l0, l1, l2, l3, bBl + kso + boff[ntp]);
#pragma unroll
                for (int mt = 0; mt < 4; mt++) {
                    mma_bf16(acc[mt][2 * ntp],     ah[mt], h0, h2);
                    mma_bf16(acc[mt][2 * ntp],     al[mt], h0, h2);
                    mma_bf16(acc[mt][2 * ntp],     ah[mt], l0, l2);
                    mma_bf16(acc[mt][2 * ntp + 1], ah[mt], h1, h3);
                    mma_bf16(acc[mt][2 * ntp + 1], al[mt], h1, h3);
                    mma_bf16(acc[mt][2 * ntp + 1], ah[mt], l1, l3);
                }
            }
        }
        __syncthreads();
    }

    // epilogue (+ optional fused gating row-dot)
    float rowacc[4][2];
#pragma unroll
    for (int i = 0; i < 4; i++) { rowacc[i][0] = 0.f; rowacc[i][1] = 0.f; }

#pragma unroll
    for (int nt = 0; nt < 4; nt++) {
        int col = n0 + wn + nt * 8 + c2;
        float b0 = bias ? bias[col] : 0.f;
        float b1 = bias ? bias[col + 1] : 0.f;
        float w0 = gvw ? gvw[col] : 0.f;
        float w1 = gvw ? gvw[col + 1] : 0.f;
#pragma unroll
        for (int mt = 0; mt < 4; mt++) {
            int row = m0 + wm + mt * 16 + r;
#pragma unroll
            for (int half = 0; half < 2; half++) {
                int rr = row + half * 8;
                float v0 = acc[mt][nt][half * 2 + 0] + b0;
                float v1 = acc[mt][nt][half * 2 + 1] + b1;
                if (act == 1) { v0 = fmaxf(v0, 0.f); v1 = fmaxf(v1, 0.f); }
                else if (act == 2) {
                    v0 = 0.5f * v0 * (1.f + erff(v0 * 0.70710678118654752f));
                    v1 = 0.5f * v1 * (1.f + erff(v1 * 0.70710678118654752f));
                }
                if (gvw) rowacc[mt][half] += v0 * w0 + v1 * w1;
                size_t o = (size_t)rr * Nout + col;
                if (Cf) *(float2*)(Cf + o) = make_float2(v0, v1);
                if (Chi) {
                    __nv_bfloat16 h0 = __float2bfloat16_rn(v0);
                    __nv_bfloat16 h1 = __float2bfloat16_rn(v1);
                    __nv_bfloat162 hp; hp.x = h0; hp.y = h1;
                    *(__nv_bfloat162*)(Chi + o) = hp;
                    __nv_bfloat162 lp;
                    lp.x = __float2bfloat16_rn(v0 - __bfloat162float(h0));
                    lp.y = __float2bfloat16_rn(v1 - __bfloat162float(h1));
                    *(__nv_bfloat162*)(Clo + o) = lp;
                }
            }
        }
    }
    if (gvw) {
#pragma unroll
        for (int mt = 0; mt < 4; mt++)
#pragma unroll
            for (int half = 0; half < 2; half++) {
                float v = rowacc[mt][half];
                v += __shfl_xor_sync(0xffffffffu, v, 1);
                v += __shfl_xor_sync(0xffffffffu, v, 2);
                if ((lane & 3) == 0) {
                    int row = m0 + wm + mt * 16 + r + half * 8;
                    atomicAdd(gso + row, v);
                }
            }
    }
}

// ---------------- fold edge projection into per-layer 32-dim vector ----------------
__global__ void wa_kernel(const float* __restrict__ We, const float* __restrict__ be,
                          const float* __restrict__ gat_a)
{
    int l = blockIdx.x;
    int t = threadIdx.x;
    const float* a = gat_a + l * (3 * HH) + 2 * HH;
    if (t < 32) {
        float s = 0.f;
        const float* row = We + t * HH;
        for (int j = 0; j < HH; j++) s += row[j] * a[j];
        g_wa[l * 32 + t] = s;
    } else if (t == 32) {
        float s = 0.f;
        for (int j = 0; j < HH; j++) s += be[j] * a[j];
        g_cb[l] = s;
    }
}

// ---------------- per-edge ce for ALL layers ----------------
__global__ __launch_bounds__(256) void ce_kernel(const float* __restrict__ ef)
{
    int e = blockIdx.x * 256 + threadIdx.x;
    float4 v[8];
    const float4* row = (const float4*)(ef + (size_t)e * 32);
#pragma unroll
    for (int i = 0; i < 8; i++) v[i] = row[i];
#pragma unroll
    for (int l = 0; l < LL; l++) {
        const float* wa = g_wa + l * 32;
        float s = g_cb[l];
#pragma unroll
        for (int i = 0; i < 8; i++) {
            s += v[i].x * wa[4 * i + 0];
            s += v[i].y * wa[4 * i + 1];
            s += v[i].z * wa[4 * i + 2];
            s += v[i].w * wa[4 * i + 3];
        }
        g_ce[l * EE + e] = s;
    }
}

// ---------------- graph-resident GAT layer (512 threads) ----------------
#define GATSM (NPG * HH * 4 + (64 + 64 + 512) * 4 + 512 * 4)

__global__ __launch_bounds__(512) void gat_layer_kernel(
    const int* __restrict__ dst, const float* __restrict__ ce_l,
    const float* __restrict__ gat_a,
    const float* __restrict__ lng, const float* __restrict__ lnb, int l)
{
    extern __shared__ float smf[];
    float* smm = smf;
    float* sas = smf + NPG * HH;
    float* sad = sas + 64;
    float* swt = sad + 64;
    int*   sdl = (int*)(swt + 512);

    const int g = blockIdx.x;
    const int t = threadIdx.x;
    const int warp = t >> 5, lane = t & 31;

    {
        const float4* src = (const float4*)(g_m + (size_t)g * NPG * HH);
        float4* dstp = (float4*)smm;
#pragma unroll
        for (int i = 0; i < 8; i++)
            dstp[t + 512 * i] = src[t + 512 * i];
    }
    __syncthreads();

    {
        const float* a1 = gat_a + l * (3 * HH);
        const float* a2 = a1 + HH;
#pragma unroll
        for (int q = 0; q < 4; q++) {
            int i = warp * 4 + q;
            const float* mr = smm + i * HH;
            float s = 0.f, d = 0.f;
#pragma unroll
            for (int j = lane; j < HH; j += 32) {
                float mv = mr[j];
                s += mv * a1[j];
                d += mv * a2[j];
            }
#pragma unroll
            for (int off = 16; off; off >>= 1) {
                s += __shfl_xor_sync(0xffffffffu, s, off);
                d += __shfl_xor_sync(0xffffffffu, d, off);
            }
            if (lane == 0) { sas[i] = s; sad[i] = d; }
        }
    }
    __syncthreads();

    if (t < NPG) {
        float lg[DEG];
        int   dl[DEG];
#pragma unroll
        for (int k = 0; k < DEG; k++) {
            int e = t * DEG + k;
            int d = dst[g * (NPG * DEG) + e] - g * NPG;
            dl[k] = d;
            float x = sas[t] + sad[d] + ce_l[g * (NPG * DEG) + e];
            lg[k] = (x >= 0.f) ? x : 0.01f * x;
        }
        float mx = -1e30f;
#pragma unroll
        for (int k = 0; k < DEG; k++) mx = fmaxf(mx, lg[k]);
        float ws = 0.f;
#pragma unroll
        for (int k = 0; k < DEG; k++) { lg[k] = __expf(lg[k] - mx); ws += lg[k]; }
        float inv = 1.f / ws;
#pragma unroll
        for (int k = 0; k < DEG; k++) {
            swt[t * DEG + k] = lg[k] * inv;
            sdl[t * DEG + k] = dl[k];
        }
    }
    __syncthreads();

#pragma unroll
    for (int q = 0; q < 4; q++) {
        int i = warp * 4 + q;
        float acc[8] = {0.f, 0.f, 0.f, 0.f, 0.f, 0.f, 0.f, 0.f};
#pragma unroll
        for (int k = 0; k < DEG; k++) {
            float wk = swt[i * DEG + k];
            const float4* mr = (const float4*)(smm + sdl[i * DEG + k] * HH) + lane * 2;
            float4 v0 = mr[0], v1 = mr[1];
            acc[0] += wk * v0.x; acc[1] += wk * v0.y;
            acc[2] += wk * v0.z; acc[3] += wk * v0.w;
            acc[4] += wk * v1.x; acc[5] += wk * v1.y;
            acc[6] += wk * v1.z; acc[7] += wk * v1.w;
        }
        size_t rowo = (size_t)(g * NPG + i) * HH + lane * 8;
        const float4* hr = (const float4*)(g_h + rowo);
        float4 h0 = hr[0], h1 = hr[1];
        float x[8];
        x[0] = acc[0] + h0.x; x[1] = acc[1] + h0.y;
        x[2] = acc[2] + h0.z; x[3] = acc[3] + h0.w;
        x[4] = acc[4] + h1.x; x[5] = acc[5] + h1.y;
        x[6] = acc[6] + h1.z; x[7] = acc[7] + h1.w;

        float s = 0.f, s2 = 0.f;
#pragma unroll
        for (int c = 0; c < 8; c++) { s += x[c]; s2 += x[c] * x[c]; }
#pragma unroll
        for (int off = 16; off; off >>= 1) {
            s  += __shfl_xor_sync(0xffffffffu, s,  off);
            s2 += __shfl_xor_sync(0xffffffffu, s2, off);
        }
        float mean = s * (1.f / HH);
        float var  = s2 * (1.f / HH) - mean * mean;
        float rstd = rsqrtf(var + 1e-5f);

        const float4* gg = (const float4*)(lng + l * HH + lane * 8);
        const float4* bb = (const float4*)(lnb + l * HH + lane * 8);
        float4 gv0 = gg[0], gv1 = gg[1];
        float4 bv0 = bb[0], bv1 = bb[1];
        float y[8];
        y[0] = (x[0] - mean) * rstd * gv0.x + bv0.x;
        y[1] = (x[1] - mean) * rstd * gv0.y + bv0.y;
        y[2] = (x[2] - mean) * rstd * gv0.z + bv0.z;
        y[3] = (x[3] - mean) * rstd * gv0.w + bv0.w;
        y[4] = (x[4] - mean) * rstd * gv1.x + bv1.x;
        y[5] = (x[5] - mean) * rstd * gv1.y + bv1.y;
        y[6] = (x[6] - mean) * rstd * gv1.z + bv1.z;
        y[7] = (x[7] - mean) * rstd * gv1.w + bv1.w;

        float4* ho = (float4*)(g_h + rowo);
        ho[0] = make_float4(y[0], y[1], y[2], y[3]);
        ho[1] = make_float4(y[4], y[5], y[6], y[7]);

        uint32_t hi[4], lo[4];
#pragma unroll
        for (int c = 0; c < 4; c++) {
            __nv_bfloat16 a0 = __float2bfloat16_rn(y[2 * c]);
            __nv_bfloat16 a1 = __float2bfloat16_rn(y[2 * c + 1]);
            __nv_bfloat162 hp; hp.x = a0; hp.y = a1;
            hi[c] = *(uint32_t*)&hp;
            __nv_bfloat162 lp;
            lp.x = __float2bfloat16_rn(y[2 * c] - __bfloat162float(a0));
            lp.y = __float2bfloat16_rn(y[2 * c + 1] - __bfloat162float(a1));
            lo[c] = *(uint32_t*)&lp;
        }
        *(uint4*)(g_h_h + rowo) = make_uint4(hi[0], hi[1], hi[2], hi[3]);
        *(uint4*)(g_h_l + rowo) = make_uint4(lo[0], lo[1], lo[2], lo[3]);
    }
}

// ---------------- residual + LayerNorm (+ optional bf16 hi/lo out) ----------------
__global__ __launch_bounds__(256) void ln_kernel(
    const float* __restrict__ xa, const float* __restrict__ xb,
    const float* __restrict__ g, const float* __restrict__ b,
    float* __restrict__ out,
    __nv_bfloat16* __restrict__ ohi, __nv_bfloat16* __restrict__ olo,
    float eps)
{
    __shared__ float rs[8], rs2[8];
    int n = blockIdx.x;
    int t = threadIdx.x;
    int warp = t >> 5, lane = t & 31;
    float x = xa[(size_t)n * HH + t] + xb[(size_t)n * HH + t];
    float s = x, s2 = x * x;
#pragma unroll
    for (int off = 16; off; off >>= 1) {
        s  += __shfl_xor_sync(0xffffffffu, s,  off);
        s2 += __shfl_xor_sync(0xffffffffu, s2, off);
    }
    if (lane == 0) { rs[warp] = s; rs2[warp] = s2; }
    __syncthreads();
    if (warp == 0) {
        float a = (lane < 8) ? rs[lane]  : 0.f;
        float c = (lane < 8) ? rs2[lane] : 0.f;
#pragma unroll
        for (int off = 4; off; off >>= 1) {
            a += __shfl_xor_sync(0xffffffffu, a, off);
            c += __shfl_xor_sync(0xffffffffu, c, off);
        }
        if (lane == 0) { rs[0] = a; rs2[0] = c; }
    }
    __syncthreads();
    float mean = rs[0] * (1.f / HH);
    float var  = rs2[0] * (1.f / HH) - mean * mean;
    float y = (x - mean) * rsqrtf(var + eps) * g[t] + b[t];
    size_t o = (size_t)n * HH + t;
    out[o] = y;
    if (ohi) {
        __nv_bfloat16 hh = __float2bfloat16_rn(y);
        ohi[o] = hh;
        olo[o] = __float2bfloat16_rn(y - __bfloat162float(hh));
    }
}

// ---------------- per-(graph, head) global attention (packed qkv) ----------------
__global__ __launch_bounds__(256) void attn_kernel()
{
    __shared__ float qs[NPG][33];
    __shared__ float ks[NPG][33];
    __shared__ float vs[NPG][DKH];
    __shared__ float pb[8][NPG];

    int head = blockIdx.x;
    int b = blockIdx.y;
    int t = threadIdx.x;
    int warp = t >> 5, lane = t & 31;

    for (int idx = t; idx < NPG * DKH; idx += 256) {
        int r = idx >> 5, d = idx & 31;
        size_t g = (size_t)(b * NPG + r) * 768 + head * DKH + d;
        qs[r][d] = g_qkv[g];
        ks[r][d] = g_qkv[g + 256];
        vs[r][d] = g_qkv[g + 512];
    }
    __syncthreads();

    const float scale = 0.17677669529663687f;
    for (int r = 0; r < 8; r++) {
        int i = warp * 8 + r;
        float s0 = 0.f, s1 = 0.f;
#pragma unroll
        for (int d = 0; d < DKH; d++) {
            float qd = qs[i][d];
            s0 += qd * ks[lane][d];
            s1 += qd * ks[lane + 32][d];
        }
        s0 *= scale; s1 *= scale;
        float mx = fmaxf(s0, s1);
#pragma unroll
        for (int off = 16; off; off >>= 1)
            mx = fmaxf(mx, __shfl_xor_sync(0xffffffffu, mx, off));
        float e0 = __expf(s0 - mx), e1 = __expf(s1 - mx);
        float sm = e0 + e1;
#pragma unroll
        for (int off = 16; off; off >>= 1)
            sm += __shfl_xor_sync(0xffffffffu, sm, off);
        float inv = 1.f / sm;
        pb[warp][lane] = e0 * inv;
        pb[warp][lane + 32] = e1 * inv;
        __syncwarp();
        float o = 0.f;
#pragma unroll
        for (int j = 0; j < NPG; j++) o += pb[warp][j] * vs[j][lane];
        g_o[(size_t)(b * NPG + i) * HH + head * DKH + lane] = o;
    }
}

// ---------------- gated readout per graph ----------------
__global__ __launch_bounds__(256) void readout_kernel(float* __restrict__ out)
{
    __shared__ float p[NPG];
    int b = blockIdx.x;
    int t = threadIdx.x;
    if (t < NPG) p[t] = g_gs[b * NPG + t];
    __syncthreads();
    float mx = -1e30f;
#pragma unroll
    for (int i = 0; i < NPG; i++) mx = fmaxf(mx, p[i]);
    float s = 0.f, acc = 0.f;
    for (int i = 0; i < NPG; i++) {
        float w = __expf(p[i] - mx);
        s += w;
        acc += w * g_h[(size_t)(b * NPG + i) * HH + t];
    }
    out[b * HH + t] = acc / s;
}

// ---------------- host launcher ----------------
static inline __nv_bfloat16* sym(const void* s)
{
    void* p = nullptr;
    cudaGetSymbolAddress(&p, s);
    return (__nv_bfloat16*)p;
}

extern "C" void kernel_launch(void* const* d_in, const int* in_sizes, int n_in,
                              void* d_out, int out_size)
{
    const float* node_feats = (const float*)d_in[0];
    const float* edge_feats = (const float*)d_in[1];
    const int*   dst        = (const int*)  d_in[3];
    const float* Wn   = (const float*)d_in[4];
    const float* bn   = (const float*)d_in[5];
    const float* We   = (const float*)d_in[6];
    const float* be   = (const float*)d_in[7];
    const float* gatW = (const float*)d_in[8];
    const float* gata = (const float*)d_in[9];
    const float* glng = (const float*)d_in[10];
    const float* glnb = (const float*)d_in[11];
    const float* Wq   = (const float*)d_in[12];
    const float* Wk   = (const float*)d_in[13];
    const float* Wv   = (const float*)d_in[14];
    const float* alng = (const float*)d_in[15];
    const float* alnb = (const float*)d_in[16];
    const float* fW1  = (const float*)d_in[17];
    const float* fb1  = (const float*)d_in[18];
    const float* fW2  = (const float*)d_in[19];
    const float* fb2  = (const float*)d_in[20];
    const float* flng = (const float*)d_in[21];
    const float* flnb = (const float*)d_in[22];
    const float* gW1  = (const float*)d_in[23];
    const float* gb1  = (const float*)d_in[24];
    const float* gW2  = (const float*)d_in[25];
    float* out = (float*)d_out;

    cudaFuncSetAttribute(gemm_tc, cudaFuncAttributeMaxDynamicSharedMemorySize,
                         SMEM_GEMM);
    cudaFuncSetAttribute(gat_layer_kernel,
                         cudaFuncAttributeMaxDynamicSharedMemorySize, GATSM);

    float *h_p, *m_p, *qkv_p, *o_p, *ce_p, *gs_p;
    cudaGetSymbolAddress((void**)&h_p, g_h);
    cudaGetSymbolAddress((void**)&m_p, g_m);
    cudaGetSymbolAddress((void**)&qkv_p, g_qkv);
    cudaGetSymbolAddress((void**)&o_p, g_o);
    cudaGetSymbolAddress((void**)&ce_p, g_ce);
    cudaGetSymbolAddress((void**)&gs_p, g_gs);

    __nv_bfloat16 *nf_h = sym(g_nf_h), *nf_l = sym(g_nf_l);
    __nv_bfloat16 *h_h = sym(g_h_h),  *h_l = sym(g_h_l);
    __nv_bfloat16 *ff_h = sym(g_ff_h), *ff_l = sym(g_ff_l);
    __nv_bfloat16 *wnt_h = sym(g_wnt_h), *wnt_l = sym(g_wnt_l);
    __nv_bfloat16 *gwt_h = sym(g_gatwt_h), *gwt_l = sym(g_gatwt_l);
    __nv_bfloat16 *qkvt_h = sym(g_qkvt_h), *qkvt_l = sym(g_qkvt_l);
    __nv_bfloat16 *f1t_h = sym(g_ff1t_h), *f1t_l = sym(g_ff1t_l);
    __nv_bfloat16 *f2t_h = sym(g_ff2t_h), *f2t_l = sym(g_ff2t_l);
    __nv_bfloat16 *g1t_h = sym(g_gw1t_h), *g1t_l = sym(g_gw1t_l);

    ConvTab tab;
    int ne = 0, blk = 0;
    auto add = [&](const float* s, __nv_bfloat16* hi, __nv_bfloat16* lo,
                   int K, int N, int tr) {
        int nb = (K * N + 1023) / 1024;
        tab.e[ne] = {s, hi, lo, K, N, tr, blk, nb};
        blk += nb; ne++;
    };
    add(Wn, wnt_h, wnt_l, 64, HH, 1);
    for (int l = 0; l < LL; l++)
        add(gatW + (size_t)l * HH * HH, gwt_h + (size_t)l * HH * HH,
            gwt_l + (size_t)l * HH * HH, HH, HH, 1);
    add(Wq, qkvt_h, qkvt_l, HH, HH, 1);
    add(Wk, qkvt_h + 256 * HH, qkvt_l + 256 * HH, HH, HH, 1);
    add(Wv, qkvt_h + 512 * HH, qkvt_l + 512 * HH, HH, HH, 1);
    add(fW1, f1t_h, f1t_l, HH, FFD, 1);
    add(fW2, f2t_h, f2t_l, FFD, HH, 1);
    add(gW1, g1t_h, g1t_l, HH, HH, 1);
    add(node_feats, nf_h, nf_l, NN, 64, 0);
    tab.n = ne;

    conv_kernel<<<blk, 256>>>(tab);
    wa_kernel<<<LL, 64>>>(We, be, gata);
    ce_kernel<<<EE / 256, 256>>>(edge_feats);
    cudaMemsetAsync(gs_p, 0, NN * sizeof(float));

    dim3 gH(HH / 128, NN / 128);     // (2, 128)
    dim3 gQKV(768 / 128, NN / 128);  // (6, 128)
    dim3 gF(FFD / 128, NN / 128);    // (4, 128)

    gemm_tc<<<gH, 256, SMEM_GEMM>>>(nf_h, nf_l, wnt_h, wnt_l, bn, h_p, h_h, h_l,
                                    nullptr, nullptr, NN, 64, HH, 0);

    for (int l = 0; l < LL; l++) {
        gemm_tc<<<gH, 256, SMEM_GEMM>>>(h_h, h_l, gwt_h + (size_t)l * HH * HH,
                                        gwt_l + (size_t)l * HH * HH, nullptr,
                                        m_p, nullptr, nullptr,
                                        nullptr, nullptr, NN, HH, HH, 0);
        gat_layer_kernel<<<GB, 512, GATSM>>>(dst, ce_p + (size_t)l * EE,
                                             gata, glng, glnb, l);
    }

    gemm_tc<<<gQKV, 256, SMEM_GEMM>>>(h_h, h_l, qkvt_h, qkvt_l, nullptr, qkv_p,
                                      nullptr, nullptr, nullptr, nullptr,
                                      NN, HH, 768, 0);
    attn_kernel<<<dim3(NHEADS, GB), 256>>>();
    ln_kernel<<<NN, 256>>>(o_p, h_p, alng, alnb, h_p, h_h, h_l, 1e-6f);

    gemm_tc<<<gF, 256, SMEM_GEMM>>>(h_h, h_l, f1t_h, f1t_l, fb1, nullptr,
                                    ff_h, ff_l, nullptr, nullptr,
                                    NN, HH, FFD, 2);
    gemm_tc<<<gH, 256, SMEM_GEMM>>>(ff_h, ff_l, f2t_h, f2t_l, fb2, m_p,
                                    nullptr, nullptr, nullptr, nullptr,
                                    NN, FFD, HH, 0);
    ln_kernel<<<NN, 256>>>(h_p, m_p, flng, flnb, h_p, h_h, h_l, 1e-6f);

    // gating: relu(x@gW1+gb1) fused with dot(gW2) into g_gs (atomic epilogue)
    gemm_tc<<<gH, 256, SMEM_GEMM>>>(h_h, h_l, g1t_h, g1t_l, gb1, nullptr,
                                    nullptr, nullptr, gW2, gs_p,
                                    NN, HH, HH, 1);
    readout_kernel<<<GB, 256>>>(out);

    (void)in_sizes; (void)n_in; (void)out_size;
}

// round 16
// speedup vs baseline: 1.5836x; 1.0198x over previous
#include <cuda_runtime.h>
#include <cuda_bf16.h>
#include <math.h>
#include <stdint.h>

// ---------------- problem constants ----------------
#define NN      16384
#define EE      131072
#define HH      256
#define LL      4
#define GB      256
#define NPG     64
#define NHEADS  8
#define DKH     32
#define DEG     8
#define FFD     512

// ---------------- fp32 scratch ----------------
__device__ float g_h[NN * HH];
__device__ float g_m[NN * HH];
__device__ float g_qkv[NN * 768];
__device__ float g_o[NN * HH];
__device__ float g_gs[NN];
__device__ float g_wa[LL * 32];
__device__ float g_cb[LL];
__device__ float g_ce[LL * EE];

// ---------------- bf16 hi/lo scratch (activations) ----------------
__device__ __nv_bfloat16 g_nf_h[NN * 64],   g_nf_l[NN * 64];
__device__ __nv_bfloat16 g_h_h[NN * HH],    g_h_l[NN * HH];
__device__ __nv_bfloat16 g_ff_h[NN * FFD],  g_ff_l[NN * FFD];

// ---------------- bf16 hi/lo weights, transposed to [N][K] ----------------
__device__ __nv_bfloat16 g_wnt_h[HH * 64],        g_wnt_l[HH * 64];
__device__ __nv_bfloat16 g_gatwt_h[LL * HH * HH], g_gatwt_l[LL * HH * HH];
__device__ __nv_bfloat16 g_qkvt_h[768 * HH], g_qkvt_l[768 * HH];
__device__ __nv_bfloat16 g_ff1t_h[FFD * HH], g_ff1t_l[FFD * HH];
__device__ __nv_bfloat16 g_ff2t_h[HH * FFD], g_ff2t_l[HH * FFD];
__device__ __nv_bfloat16 g_gw1t_h[HH * HH],  g_gw1t_l[HH * HH];

// ======== conversion: fp32 -> (bf16 hi, lo); tiled transpose for weights ========
struct ConvEnt {
    const float* src;
    __nv_bfloat16* hi;
    __nv_bfloat16* lo;
    int K, N, trans, blk0, nblk;
};
struct ConvTab { ConvEnt e[13]; int n; };

__global__ __launch_bounds__(256) void conv_kernel(ConvTab tab)
{
    __shared__ uint32_t sh[32][33];
    __shared__ uint32_t sl[32][33];

    int b = blockIdx.x;
    int ei = 0;
    for (int i = 0; i < tab.n; i++)
        if (b >= tab.e[i].blk0) ei = i;
    ConvEnt e = tab.e[ei];
    int lb = b - e.blk0;
    const int t = threadIdx.x;

    if (!e.trans) {
        // already-coalesced path (node_feats)
        int total = e.K * e.N;
        int base = lb * 1024;
#pragma unroll
        for (int j = 0; j < 4; j++) {
            int i = base + j * 256 + t;
            if (i < total) {
                float x = e.src[i];
                __nv_bfloat16 h = __float2bfloat16_rn(x);
                e.hi[i] = h;
                e.lo[i] = __float2bfloat16_rn(x - __bfloat162float(h));
            }
        }
        return;
    }

    // tiled 32x32 transpose: src [K][N] -> dst [N][K]
    const int ntn = e.N >> 5;
    const int tk0 = (lb / ntn) << 5;
    const int tn0 = (lb % ntn) << 5;
    const int ty = t >> 5, tx = t & 31;

#pragma unroll
    for (int i = 0; i < 4; i++) {
        int k = tk0 + ty + 8 * i;
        int n = tn0 + tx;
        float x = e.src[(size_t)k * e.N + n];
        __nv_bfloat16 h = __float2bfloat16_rn(x);
        __nv_bfloat16 l = __float2bfloat16_rn(x - __bfloat162float(h));
        sh[ty + 8 * i][tx] = (uint32_t)(*(unsigned short*)&h);
        sl[ty + 8 * i][tx] = (uint32_t)(*(unsigned short*)&l);
    }
    __syncthreads();

#pragma unroll
    for (int i = 0; i < 4; i++) {
        int n = tn0 + ty + 8 * i;
        int k = tk0 + tx;
        unsigned short hv = (unsigned short)sh[tx][ty + 8 * i];
        unsigned short lv = (unsigned short)sl[tx][ty + 8 * i];
        size_t di = (size_t)n * e.K + k;
        *(unsigned short*)&e.hi[di] = hv;
        *(unsigned short*)&e.lo[di] = lv;
    }
}

// ================= pipelined tensor-core GEMM (R11 config + fused gate) ======
#define SA   40
#define BUFE (128 * SA)
#define SMEM_GEMM (8 * BUFE * 2)

__device__ __forceinline__ void mma_bf16(float* c, const uint32_t* a,
                                         uint32_t b0, uint32_t b1)
{
    asm volatile(
        "mma.sync.aligned.m16n8k16.row.col.f32.bf16.bf16.f32 "
        "{%0,%1,%2,%3}, {%4,%5,%6,%7}, {%8,%9}, {%0,%1,%2,%3};\n"
        : "+f"(c[0]), "+f"(c[1]), "+f"(c[2]), "+f"(c[3])
        : "r"(a[0]), "r"(a[1]), "r"(a[2]), "r"(a[3]), "r"(b0), "r"(b1));
}

__device__ __forceinline__ void cp16(void* s, const void* g)
{
    uint32_t sa = (uint32_t)__cvta_generic_to_shared(s);
    asm volatile("cp.async.ca.shared.global [%0], [%1], 16;\n" :: "r"(sa), "l"(g));
}

__device__ __forceinline__ void ldmat4(uint32_t& r0, uint32_t& r1,
                                       uint32_t& r2, uint32_t& r3, uint32_t addr)
{
    asm volatile("ldmatrix.sync.aligned.m8n8.x4.shared.b16 {%0,%1,%2,%3}, [%4];\n"
                 : "=r"(r0), "=r"(r1), "=r"(r2), "=r"(r3) : "r"(addr));
}

__global__ __launch_bounds__(256, 2) void gemm_tc(
    const __nv_bfloat16* __restrict__ Ah, const __nv_bfloat16* __restrict__ Al,
    const __nv_bfloat16* __restrict__ Bh, const __nv_bfloat16* __restrict__ Bl,
    const float* __restrict__ bias,
    float* __restrict__ Cf,
    __nv_bfloat16* __restrict__ Chi, __nv_bfloat16* __restrict__ Clo,
    const float* __restrict__ gvw, float* __restrict__ gso,
    int M, int K, int Nout, int act)
{
    extern __shared__ __nv_bfloat16 sm[];
    __nv_bfloat16* sAh = sm;
    __nv_bfloat16* sAl = sm + 2 * BUFE;
    __nv_bfloat16* sBh = sm + 4 * BUFE;
    __nv_bfloat16* sBl = sm + 6 * BUFE;

    const int t = threadIdx.x;
    const int warp = t >> 5, lane = t & 31;
    const int wm = (warp & 1) * 64;
    const int wn = (warp >> 1) * 32;
    const int r = lane >> 2, c2 = (lane & 3) * 2;
    const int m0 = blockIdx.y * 128;
    const int n0 = blockIdx.x * 128;

    const int lr = t >> 2;
    const int lc = (t & 3) * 8;

    const int g8 = lane >> 3;
    const int lrow = (g8 & 1) * 8 + (lane & 7);
    const int kof = (g8 >> 1) * 8;

    float acc[4][4][4];
#pragma unroll
    for (int i = 0; i < 4; i++)
#pragma unroll
        for (int j = 0; j < 4; j++)
#pragma unroll
            for (int k = 0; k < 4; k++) acc[i][j][k] = 0.f;

    const __nv_bfloat16* pAh = Ah + (size_t)(m0 + lr) * K + lc;
    const __nv_bfloat16* pAl = Al + (size_t)(m0 + lr) * K + lc;
    const __nv_bfloat16* pBh = Bh + (size_t)(n0 + lr) * K + lc;
    const __nv_bfloat16* pBl = Bl + (size_t)(n0 + lr) * K + lc;
    const size_t rs64 = (size_t)64 * K;

    const int so0 = lr * SA + lc;
    const int so1 = (lr + 64) * SA + lc;

    uint32_t bAh = (uint32_t)__cvta_generic_to_shared(sAh);
    uint32_t bAl = (uint32_t)__cvta_generic_to_shared(sAl);
    uint32_t bBh = (uint32_t)__cvta_generic_to_shared(sBh);
    uint32_t bBl = (uint32_t)__cvta_generic_to_shared(sBl);

    uint32_t aoff[4], boff[2];
#pragma unroll
    for (int mt = 0; mt < 4; mt++)
        aoff[mt] = ((wm + mt * 16 + lrow) * SA + kof) * 2;
#pragma unroll
    for (int ntp = 0; ntp < 2; ntp++)
        boff[ntp] = ((wn + ntp * 16 + lrow) * SA + kof) * 2;

    cp16(&sAh[so0], pAh);            cp16(&sAh[so1], pAh + rs64);
    cp16(&sAl[so0], pAl);            cp16(&sAl[so1], pAl + rs64);
    cp16(&sBh[so0], pBh);            cp16(&sBh[so1], pBh + rs64);
    cp16(&sBl[so0], pBl);            cp16(&sBl[so1], pBl + rs64);
    asm volatile("cp.async.commit_group;\n");

    const int nIter = K >> 5;
    for (int i = 0; i < nIter; i++) {
        const int s = i & 1;
        if (i + 1 < nIter) {
            int k0 = (i + 1) << 5;
            int nso = ((i + 1) & 1) * BUFE;
            cp16(&sAh[nso + so0], pAh + k0);  cp16(&sAh[nso + so1], pAh + rs64 + k0);
            cp16(&sAl[nso + so0], pAl + k0);  cp16(&sAl[nso + so1], pAl + rs64 + k0);
            cp16(&sBh[nso + so0], pBh + k0);  cp16(&sBh[nso + so1], pBh + rs64 + k0);
            cp16(&sBl[nso + so0], pBl + k0);  cp16(&sBl[nso + so1], pBl + rs64 + k0);
            asm volatile("cp.async.commit_group;\n");
            asm volatile("cp.async.wait_group 1;\n");
        } else {
            asm volatile("cp.async.wait_group 0;\n");
        }
        __syncthreads();

        const uint32_t sb = s * BUFE * 2;
#pragma unroll
        for (int ks = 0; ks < 2; ks++) {
            const uint32_t kso = sb + ks * 32;
            uint32_t ah[4][4], al[4][4];
#pragma unroll
            for (int mt = 0; mt < 4; mt++) {
                ldmat4(ah[mt][0], ah[mt][1], ah[mt][2], ah[mt][3], bAh + kso + aoff[mt]);
                ldmat4(al[mt][0], al[mt][1], al[mt][2], al[mt][3], bAl + kso + aoff[mt]);
            }
#pragma unroll
            for (int ntp = 0; ntp < 2; ntp++) {
                uint32_t h0, h1, h2, h3, l0, l1, l2, l3;
                ldmat4(h0, h1, h2, h3, bBh + kso + boff[ntp]);
                ldmat4(l0, l1, l2, l3, bBl + kso + boff[ntp]);
#pragma unroll
                for (int mt = 0; mt < 4; mt++) {
                    mma_bf16(acc[mt][2 * ntp],     ah[mt], h0, h2);
                    mma_bf16(acc[mt][2 * ntp],     al[mt], h0, h2);
                    mma_bf16(acc[mt][2 * ntp],     ah[mt], l0, l2);
                    mma_bf16(acc[mt][2 * ntp + 1], ah[mt], h1, h3);
                    mma_bf16(acc[mt][2 * ntp + 1], al[mt], h1, h3);
                    mma_bf16(acc[mt][2 * ntp + 1], ah[mt], l1, l3);
                }
            }
        }
        __syncthreads();
    }

    // epilogue (+ optional fused gating row-dot)
    float rowacc[4][2];
#pragma unroll
    for (int i = 0; i < 4; i++) { rowacc[i][0] = 0.f; rowacc[i][1] = 0.f; }

#pragma unroll
    for (int nt = 0; nt < 4; nt++) {
        int col = n0 + wn + nt * 8 + c2;
        float b0 = bias ? bias[col] : 0.f;
        float b1 = bias ? bias[col + 1] : 0.f;
        float w0 = gvw ? gvw[col] : 0.f;
        float w1 = gvw ? gvw[col + 1] : 0.f;
#pragma unroll
        for (int mt = 0; mt < 4; mt++) {
            int row = m0 + wm + mt * 16 + r;
#pragma unroll
            for (int half = 0; half < 2; half++) {
                int rr = row + half * 8;
                float v0 = acc[mt][nt][half * 2 + 0] + b0;
                float v1 = acc[mt][nt][half * 2 + 1] + b1;
                if (act == 1) { v0 = fmaxf(v0, 0.f); v1 = fmaxf(v1, 0.f); }
                else if (act == 2) {
                    v0 = 0.5f * v0 * (1.f + erff(v0 * 0.70710678118654752f));
                    v1 = 0.5f * v1 * (1.f + erff(v1 * 0.70710678118654752f));
                }
                if (gvw) rowacc[mt][half] += v0 * w0 + v1 * w1;
                size_t o = (size_t)rr * Nout + col;
                if (Cf) *(float2*)(Cf + o) = make_float2(v0, v1);
                if (Chi) {
                    __nv_bfloat16 h0 = __float2bfloat16_rn(v0);
                    __nv_bfloat16 h1 = __float2bfloat16_rn(v1);
                    __nv_bfloat162 hp; hp.x = h0; hp.y = h1;
                    *(__nv_bfloat162*)(Chi + o) = hp;
                    __nv_bfloat162 lp;
                    lp.x = __float2bfloat16_rn(v0 - __bfloat162float(h0));
                    lp.y = __float2bfloat16_rn(v1 - __bfloat162float(h1));
                    *(__nv_bfloat162*)(Clo + o) = lp;
                }
            }
        }
    }
    if (gvw) {
#pragma unroll
        for (int mt = 0; mt < 4; mt++)
#pragma unroll
            for (int half = 0; half < 2; half++) {
                float v = rowacc[mt][half];
                v += __shfl_xor_sync(0xffffffffu, v, 1);
                v += __shfl_xor_sync(0xffffffffu, v, 2);
                if ((lane & 3) == 0) {
                    int row = m0 + wm + mt * 16 + r + half * 8;
                    atomicAdd(gso + row, v);
                }
            }
    }
}

// ---------------- fold edge projection into per-layer 32-dim vector ----------------
__global__ void wa_kernel(const float* __restrict__ We, const float* __restrict__ be,
                          const float* __restrict__ gat_a)
{
    int l = blockIdx.x;
    int t = threadIdx.x;
    const float* a = gat_a + l * (3 * HH) + 2 * HH;
    if (t < 32) {
        float s = 0.f;
        const float* row = We + t * HH;
        for (int j = 0; j < HH; j++) s += row[j] * a[j];
        g_wa[l * 32 + t] = s;
    } else if (t == 32) {
        float s = 0.f;
        for (int j = 0; j < HH; j++) s += be[j] * a[j];
        g_cb[l] = s;
    }
}

// ---------------- per-edge ce for ALL layers ----------------
__global__ __launch_bounds__(256) void ce_kernel(const float* __restrict__ ef)
{
    int e = blockIdx.x * 256 + threadIdx.x;
    float4 v[8];
    const float4* row = (const float4*)(ef + (size_t)e * 32);
#pragma unroll
    for (int i = 0; i < 8; i++) v[i] = row[i];
#pragma unroll
    for (int l = 0; l < LL; l++) {
        const float* wa = g_wa + l * 32;
        float s = g_cb[l];
#pragma unroll
        for (int i = 0; i < 8; i++) {
            s += v[i].x * wa[4 * i + 0];
            s += v[i].y * wa[4 * i + 1];
            s += v[i].z * wa[4 * i + 2];
            s += v[i].w * wa[4 * i + 3];
        }
        g_ce[l * EE + e] = s;
    }
}

// ---------------- graph-resident GAT layer (512 threads) ----------------
#define GATSM (NPG * HH * 4 + (64 + 64 + 512) * 4 + 512 * 4)

__global__ __launch_bounds__(512) void gat_layer_kernel(
    const int* __restrict__ dst, const float* __restrict__ ce_l,
    const float* __restrict__ gat_a,
    const float* __restrict__ lng, const float* __restrict__ lnb, int l)
{
    extern __shared__ float smf[];
    float* smm = smf;
    float* sas = smf + NPG * HH;
    float* sad = sas + 64;
    float* swt = sad + 64;
    int*   sdl = (int*)(swt + 512);

    const int g = blockIdx.x;
    const int t = threadIdx.x;
    const int warp = t >> 5, lane = t & 31;

    {
        const float4* src = (const float4*)(g_m + (size_t)g * NPG * HH);
        float4* dstp = (float4*)smm;
#pragma unroll
        for (int i = 0; i < 8; i++)
            dstp[t + 512 * i] = src[t + 512 * i];
    }
    __syncthreads();

    {
        const float* a1 = gat_a + l * (3 * HH);
        const float* a2 = a1 + HH;
#pragma unroll
        for (int q = 0; q < 4; q++) {
            int i = warp * 4 + q;
            const float* mr = smm + i * HH;
            float s = 0.f, d = 0.f;
#pragma unroll
            for (int j = lane; j < HH; j += 32) {
                float mv = mr[j];
                s += mv * a1[j];
                d += mv * a2[j];
            }
#pragma unroll
            for (int off = 16; off; off >>= 1) {
                s += __shfl_xor_sync(0xffffffffu, s, off);
                d += __shfl_xor_sync(0xffffffffu, d, off);
            }
            if (lane == 0) { sas[i] = s; sad[i] = d; }
        }
    }
    __syncthreads();

    if (t < NPG) {
        float lg[DEG];
        int   dl[DEG];
#pragma unroll
        for (int k = 0; k < DEG; k++) {
            int e = t * DEG + k;
            int d = dst[g * (NPG * DEG) + e] - g * NPG;
            dl[k] = d;
            float x = sas[t] + sad[d] + ce_l[g * (NPG * DEG) + e];
            lg[k] = (x >= 0.f) ? x : 0.01f * x;
        }
        float mx = -1e30f;
#pragma unroll
        for (int k = 0; k < DEG; k++) mx = fmaxf(mx, lg[k]);
        float ws = 0.f;
#pragma unroll
        for (int k = 0; k < DEG; k++) { lg[k] = __expf(lg[k] - mx); ws += lg[k]; }
        float inv = 1.f / ws;
#pragma unroll
        for (int k = 0; k < DEG; k++) {
            swt[t * DEG + k] = lg[k] * inv;
            sdl[t * DEG + k] = dl[k];
        }
    }
    __syncthreads();

#pragma unroll
    for (int q = 0; q < 4; q++) {
        int i = warp * 4 + q;
        float acc[8] = {0.f, 0.f, 0.f, 0.f, 0.f, 0.f, 0.f, 0.f};
#pragma unroll
        for (int k = 0; k < DEG; k++) {
            float wk = swt[i * DEG + k];
            const float4* mr = (const float4*)(smm + sdl[i * DEG + k] * HH) + lane * 2;
            float4 v0 = mr[0], v1 = mr[1];
            acc[0] += wk * v0.x; acc[1] += wk * v0.y;
            acc[2] += wk * v0.z; acc[3] += wk * v0.w;
            acc[4] += wk * v1.x; acc[5] += wk * v1.y;
            acc[6] += wk * v1.z; acc[7] += wk * v1.w;
        }
        size_t rowo = (size_t)(g * NPG + i) * HH + lane * 8;
        const float4* hr = (const float4*)(g_h + rowo);
        float4 h0 = hr[0], h1 = hr[1];
        float x[8];
        x[0] = acc[0] + h0.x; x[1] = acc[1] + h0.y;
        x[2] = acc[2] + h0.z; x[3] = acc[3] + h0.w;
        x[4] = acc[4] + h1.x; x[5] = acc[5] + h1.y;
        x[6] = acc[6] + h1.z; x[7] = acc[7] + h1.w;

        float s = 0.f, s2 = 0.f;
#pragma unroll
        for (int c = 0; c < 8; c++) { s += x[c]; s2 += x[c] * x[c]; }
#pragma unroll
        for (int off = 16; off; off >>= 1) {
            s  += __shfl_xor_sync(0xffffffffu, s,  off);
            s2 += __shfl_xor_sync(0xffffffffu, s2, off);
        }
        float mean = s * (1.f / HH);
        float var  = s2 * (1.f / HH) - mean * mean;
        float rstd = rsqrtf(var + 1e-5f);

        const float4* gg = (const float4*)(lng + l * HH + lane * 8);
        const float4* bb = (const float4*)(lnb + l * HH + lane * 8);
        float4 gv0 = gg[0], gv1 = gg[1];
        float4 bv0 = bb[0], bv1 = bb[1];
        float y[8];
        y[0] = (x[0] - mean) * rstd * gv0.x + bv0.x;
        y[1] = (x[1] - mean) * rstd * gv0.y + bv0.y;
        y[2] = (x[2] - mean) * rstd * gv0.z + bv0.z;
        y[3] = (x[3] - mean) * rstd * gv0.w + bv0.w;
        y[4] = (x[4] - mean) * rstd * gv1.x + bv1.x;
        y[5] = (x[5] - mean) * rstd * gv1.y + bv1.y;
        y[6] = (x[6] - mean) * rstd * gv1.z + bv1.z;
        y[7] = (x[7] - mean) * rstd * gv1.w + bv1.w;

        float4* ho = (float4*)(g_h + rowo);
        ho[0] = make_float4(y[0], y[1], y[2], y[3]);
        ho[1] = make_float4(y[4], y[5], y[6], y[7]);

        uint32_t hi[4], lo[4];
#pragma unroll
        for (int c = 0; c < 4; c++) {
            __nv_bfloat16 a0 = __float2bfloat16_rn(y[2 * c]);
            __nv_bfloat16 a1 = __float2bfloat16_rn(y[2 * c + 1]);
            __nv_bfloat162 hp; hp.x = a0; hp.y = a1;
            hi[c] = *(uint32_t*)&hp;
            __nv_bfloat162 lp;
            lp.x = __float2bfloat16_rn(y[2 * c] - __bfloat162float(a0));
            lp.y = __float2bfloat16_rn(y[2 * c + 1] - __bfloat162float(a1));
            lo[c] = *(uint32_t*)&lp;
        }
        *(uint4*)(g_h_h + rowo) = make_uint4(hi[0], hi[1], hi[2], hi[3]);
        *(uint4*)(g_h_l + rowo) = make_uint4(lo[0], lo[1], lo[2], lo[3]);
    }
}

// ---------------- residual + LayerNorm (+ optional bf16 hi/lo out) ----------------
__global__ __launch_bounds__(256) void ln_kernel(
    const float* __restrict__ xa, const float* __restrict__ xb,
    const float* __restrict__ g, const float* __restrict__ b,
    float* __restrict__ out,
    __nv_bfloat16* __restrict__ ohi, __nv_bfloat16* __restrict__ olo,
    float eps)
{
    __shared__ float rs[8], rs2[8];
    int n = blockIdx.x;
    int t = threadIdx.x;
    int warp = t >> 5, lane = t & 31;
    float x = xa[(size_t)n * HH + t] + xb[(size_t)n * HH + t];
    float s = x, s2 = x * x;
#pragma unroll
    for (int off = 16; off; off >>= 1) {
        s  += __shfl_xor_sync(0xffffffffu, s,  off);
        s2 += __shfl_xor_sync(0xffffffffu, s2, off);
    }
    if (lane == 0) { rs[warp] = s; rs2[warp] = s2; }
    __syncthreads();
    if (warp == 0) {
        float a = (lane < 8) ? rs[lane]  : 0.f;
        float c = (lane < 8) ? rs2[lane] : 0.f;
#pragma unroll
        for (int off = 4; off; off >>= 1) {
            a += __shfl_xor_sync(0xffffffffu, a, off);
            c += __shfl_xor_sync(0xffffffffu, c, off);
        }
        if (lane == 0) { rs[0] = a; rs2[0] = c; }
    }
    __syncthreads();
    float mean = rs[0] * (1.f / HH);
    float var  = rs2[0] * (1.f / HH) - mean * mean;
    float y = (x - mean) * rsqrtf(var + eps) * g[t] + b[t];
    size_t o = (size_t)n * HH + t;
    out[o] = y;
    if (ohi) {
        __nv_bfloat16 hh = __float2bfloat16_rn(y);
        ohi[o] = hh;
        olo[o] = __float2bfloat16_rn(y - __bfloat162float(hh));
    }
}

// ---------------- per-(graph, head) global attention (packed qkv) ----------------
__global__ __launch_bounds__(256) void attn_kernel()
{
    __shared__ float qs[NPG][33];
    __shared__ float ks[NPG][33];
    __shared__ float vs[NPG][DKH];
    __shared__ float pb[8][NPG];

    int head = blockIdx.x;
    int b = blockIdx.y;
    int t = threadIdx.x;
    int warp = t >> 5, lane = t & 31;

    for (int idx = t; idx < NPG * DKH; idx += 256) {
        int r = idx >> 5, d = idx & 31;
        size_t g = (size_t)(b * NPG + r) * 768 + head * DKH + d;
        qs[r][d] = g_qkv[g];
        ks[r][d] = g_qkv[g + 256];
        vs[r][d] = g_qkv[g + 512];
    }
    __syncthreads();

    const float scale = 0.17677669529663687f;
    for (int r = 0; r < 8; r++) {
        int i = warp * 8 + r;
        float s0 = 0.f, s1 = 0.f;
#pragma unroll
        for (int d = 0; d < DKH; d++) {
            float qd = qs[i][d];
            s0 += qd * ks[lane][d];
            s1 += qd * ks[lane + 32][d];
        }
        s0 *= scale; s1 *= scale;
        float mx = fmaxf(s0, s1);
#pragma unroll
        for (int off = 16; off; off >>= 1)
            mx = fmaxf(mx, __shfl_xor_sync(0xffffffffu, mx, off));
        float e0 = __expf(s0 - mx), e1 = __expf(s1 - mx);
        float sm = e0 + e1;
#pragma unroll
        for (int off = 16; off; off >>= 1)
            sm += __shfl_xor_sync(0xffffffffu, sm, off);
        float inv = 1.f / sm;
        pb[warp][lane] = e0 * inv;
        pb[warp][lane + 32] = e1 * inv;
        __syncwarp();
        float o = 0.f;
#pragma unroll
        for (int j = 0; j < NPG; j++) o += pb[warp][j] * vs[j][lane];
        g_o[(size_t)(b * NPG + i) * HH + head * DKH + lane] = o;
    }
}

// ---------------- gated readout per graph ----------------
__global__ __launch_bounds__(256) void readout_kernel(float* __restrict__ out)
{
    __shared__ float p[NPG];
    int b = blockIdx.x;
    int t = threadIdx.x;
    if (t < NPG) p[t] = g_gs[b * NPG + t];
    __syncthreads();
    float mx = -1e30f;
#pragma unroll
    for (int i = 0; i < NPG; i++) mx = fmaxf(mx, p[i]);
    float s = 0.f, acc = 0.f;
    for (int i = 0; i < NPG; i++) {
        float w = __expf(p[i] - mx);
        s += w;
        acc += w * g_h[(size_t)(b * NPG + i) * HH + t];
    }
    out[b * HH + t] = acc / s;
}

// ---------------- host launcher ----------------
static inline __nv_bfloat16* sym(const void* s)
{
    void* p = nullptr;
    cudaGetSymbolAddress(&p, s);
    return (__nv_bfloat16*)p;
}

extern "C" void kernel_launch(void* const* d_in, const int* in_sizes, int n_in,
                              void* d_out, int out_size)
{
    const float* node_feats = (const float*)d_in[0];
    const float* edge_feats = (const float*)d_in[1];
    const int*   dst        = (const int*)  d_in[3];
    const float* Wn   = (const float*)d_in[4];
    const float* bn   = (const float*)d_in[5];
    const float* We   = (const float*)d_in[6];
    const float* be   = (const float*)d_in[7];
    const float* gatW = (const float*)d_in[8];
    const float* gata = (const float*)d_in[9];
    const float* glng = (const float*)d_in[10];
    const float* glnb = (const float*)d_in[11];
    const float* Wq   = (const float*)d_in[12];
    const float* Wk   = (const float*)d_in[13];
    const float* Wv   = (const float*)d_in[14];
    const float* alng = (const float*)d_in[15];
    const float* alnb = (const float*)d_in[16];
    const float* fW1  = (const float*)d_in[17];
    const float* fb1  = (const float*)d_in[18];
    const float* fW2  = (const float*)d_in[19];
    const float* fb2  = (const float*)d_in[20];
    const float* flng = (const float*)d_in[21];
    const float* flnb = (const float*)d_in[22];
    const float* gW1  = (const float*)d_in[23];
    const float* gb1  = (const float*)d_in[24];
    const float* gW2  = (const float*)d_in[25];
    float* out = (float*)d_out;

    cudaFuncSetAttribute(gemm_tc, cudaFuncAttributeMaxDynamicSharedMemorySize,
                         SMEM_GEMM);
    cudaFuncSetAttribute(gat_layer_kernel,
                         cudaFuncAttributeMaxDynamicSharedMemorySize, GATSM);

    float *h_p, *m_p, *qkv_p, *o_p, *ce_p, *gs_p;
    cudaGetSymbolAddress((void**)&h_p, g_h);
    cudaGetSymbolAddress((void**)&m_p, g_m);
    cudaGetSymbolAddress((void**)&qkv_p, g_qkv);
    cudaGetSymbolAddress((void**)&o_p, g_o);
    cudaGetSymbolAddress((void**)&ce_p, g_ce);
    cudaGetSymbolAddress((void**)&gs_p, g_gs);

    __nv_bfloat16 *nf_h = sym(g_nf_h), *nf_l = sym(g_nf_l);
    __nv_bfloat16 *h_h = sym(g_h_h),  *h_l = sym(g_h_l);
    __nv_bfloat16 *ff_h = sym(g_ff_h), *ff_l = sym(g_ff_l);
    __nv_bfloat16 *wnt_h = sym(g_wnt_h), *wnt_l = sym(g_wnt_l);
    __nv_bfloat16 *gwt_h = sym(g_gatwt_h), *gwt_l = sym(g_gatwt_l);
    __nv_bfloat16 *qkvt_h = sym(g_qkvt_h), *qkvt_l = sym(g_qkvt_l);
    __nv_bfloat16 *f1t_h = sym(g_ff1t_h), *f1t_l = sym(g_ff1t_l);
    __nv_bfloat16 *f2t_h = sym(g_ff2t_h), *f2t_l = sym(g_ff2t_l);
    __nv_bfloat16 *g1t_h = sym(g_gw1t_h), *g1t_l = sym(g_gw1t_l);

    ConvTab tab;
    int ne = 0, blk = 0;
    auto add = [&](const float* s, __nv_bfloat16* hi, __nv_bfloat16* lo,
                   int K, int N, int tr) {
        int nb = (K * N + 1023) / 1024;
        tab.e[ne] = {s, hi, lo, K, N, tr, blk, nb};
        blk += nb; ne++;
    };
    add(Wn, wnt_h, wnt_l, 64, HH, 1);
    for (int l = 0; l < LL; l++)
        add(gatW + (size_t)l * HH * HH, gwt_h + (size_t)l * HH * HH,
            gwt_l + (size_t)l * HH * HH, HH, HH, 1);
    add(Wq, qkvt_h, qkvt_l, HH, HH, 1);
    add(Wk, qkvt_h + 256 * HH, qkvt_l + 256 * HH, HH, HH, 1);
    add(Wv, qkvt_h + 512 * HH, qkvt_l + 512 * HH, HH, HH, 1);
    add(fW1, f1t_h, f1t_l, HH, FFD, 1);
    add(fW2, f2t_h, f2t_l, FFD, HH, 1);
    add(gW1, g1t_h, g1t_l, HH, HH, 1);
    add(node_feats, nf_h, nf_l, NN, 64, 0);
    tab.n = ne;

    conv_kernel<<<blk, 256>>>(tab);
    wa_kernel<<<LL, 64>>>(We, be, gata);
    ce_kernel<<<EE / 256, 256>>>(edge_feats);
    cudaMemsetAsync(gs_p, 0, NN * sizeof(float));

    dim3 gH(HH / 128, NN / 128);     // (2, 128)
    dim3 gQKV(768 / 128, NN / 128);  // (6, 128)
    dim3 gF(FFD / 128, NN / 128);    // (4, 128)

    gemm_tc<<<gH, 256, SMEM_GEMM>>>(nf_h, nf_l, wnt_h, wnt_l, bn, h_p, h_h, h_l,
                                    nullptr, nullptr, NN, 64, HH, 0);

    for (int l = 0; l < LL; l++) {
        gemm_tc<<<gH, 256, SMEM_GEMM>>>(h_h, h_l, gwt_h + (size_t)l * HH * HH,
                                        gwt_l + (size_t)l * HH * HH, nullptr,
                                        m_p, nullptr, nullptr,
                                        nullptr, nullptr, NN, HH, HH, 0);
        gat_layer_kernel<<<GB, 512, GATSM>>>(dst, ce_p + (size_t)l * EE,
                                             gata, glng, glnb, l);
    }

    gemm_tc<<<gQKV, 256, SMEM_GEMM>>>(h_h, h_l, qkvt_h, qkvt_l, nullptr, qkv_p,
                                      nullptr, nullptr, nullptr, nullptr,
                                      NN, HH, 768, 0);
    attn_kernel<<<dim3(NHEADS, GB), 256>>>();
    ln_kernel<<<NN, 256>>>(o_p, h_p, alng, alnb, h_p, h_h, h_l, 1e-6f);

    gemm_tc<<<gF, 256, SMEM_GEMM>>>(h_h, h_l, f1t_h, f1t_l, fb1, nullptr,
                                    ff_h, ff_l, nullptr, nullptr,
                                    NN, HH, FFD, 2);
    gemm_tc<<<gH, 256, SMEM_GEMM>>>(ff_h, ff_l, f2t_h, f2t_l, fb2, m_p,
                                    nullptr, nullptr, nullptr, nullptr,
                                    NN, FFD, HH, 0);
    ln_kernel<<<NN, 256>>>(h_p, m_p, flng, flnb, h_p, h_h, h_l, 1e-6f);

    // gating: relu(x@gW1+gb1) fused with dot(gW2) into g_gs (atomic epilogue)
    gemm_tc<<<gH, 256, SMEM_GEMM>>>(h_h, h_l, g1t_h, g1t_l, gb1, nullptr,
                                    nullptr, nullptr, gW2, gs_p,
                                    NN, HH, HH, 1);
    readout_kernel<<<GB, 256>>>(out);

    (void)in_sizes; (void)n_in; (void)out_size;
}

// round 17
// speedup vs baseline: 1.5913x; 1.0049x over previous
#include <cuda_runtime.h>
#include <cuda_bf16.h>
#include <math.h>
#include <stdint.h>

// ---------------- problem constants ----------------
#define NN      16384
#define EE      131072
#define HH      256
#define LL      4
#define GB      256
#define NPG     64
#define NHEADS  8
#define DKH     32
#define DEG     8
#define FFD     512

// ---------------- fp32 scratch ----------------
__device__ float g_h[NN * HH];
__device__ float g_m[NN * HH];
__device__ float g_qkv[NN * 768];
__device__ float g_o[NN * HH];
__device__ float g_gs[NN];
__device__ float g_wa[LL * 32];
__device__ float g_cb[LL];
__device__ float g_ce[LL * EE];

// ---------------- bf16 hi/lo scratch (activations) ----------------
__device__ __nv_bfloat16 g_nf_h[NN * 64],   g_nf_l[NN * 64];
__device__ __nv_bfloat16 g_h_h[NN * HH],    g_h_l[NN * HH];
__device__ __nv_bfloat16 g_ff_h[NN * FFD],  g_ff_l[NN * FFD];

// ---------------- bf16 hi/lo weights, transposed to [N][K] ----------------
__device__ __nv_bfloat16 g_wnt_h[HH * 64],        g_wnt_l[HH * 64];
__device__ __nv_bfloat16 g_gatwt_h[LL * HH * HH], g_gatwt_l[LL * HH * HH];
__device__ __nv_bfloat16 g_qkvt_h[768 * HH], g_qkvt_l[768 * HH];
__device__ __nv_bfloat16 g_ff1t_h[FFD * HH], g_ff1t_l[FFD * HH];
__device__ __nv_bfloat16 g_ff2t_h[HH * FFD], g_ff2t_l[HH * FFD];
__device__ __nv_bfloat16 g_gw1t_h[HH * HH],  g_gw1t_l[HH * HH];

// ======== conversion: fp32 -> (bf16 hi, lo); tiled transpose for weights ========
struct ConvEnt {
    const float* src;
    __nv_bfloat16* hi;
    __nv_bfloat16* lo;
    int K, N, trans, blk0, nblk;
};
struct ConvTab { ConvEnt e[13]; int n; };

__global__ __launch_bounds__(256) void conv_kernel(ConvTab tab)
{
    __shared__ uint32_t sh[32][33];
    __shared__ uint32_t sl[32][33];

    int b = blockIdx.x;
    int ei = 0;
    for (int i = 0; i < tab.n; i++)
        if (b >= tab.e[i].blk0) ei = i;
    ConvEnt e = tab.e[ei];
    int lb = b - e.blk0;
    const int t = threadIdx.x;

    if (!e.trans) {
        int total = e.K * e.N;
        int base = lb * 1024;
#pragma unroll
        for (int j = 0; j < 4; j++) {
            int i = base + j * 256 + t;
            if (i < total) {
                float x = e.src[i];
                __nv_bfloat16 h = __float2bfloat16_rn(x);
                e.hi[i] = h;
                e.lo[i] = __float2bfloat16_rn(x - __bfloat162float(h));
            }
        }
        return;
    }

    // tiled 32x32 transpose: src [K][N] -> dst [N][K]
    const int ntn = e.N >> 5;
    const int tk0 = (lb / ntn) << 5;
    const int tn0 = (lb % ntn) << 5;
    const int ty = t >> 5, tx = t & 31;

#pragma unroll
    for (int i = 0; i < 4; i++) {
        int k = tk0 + ty + 8 * i;
        int n = tn0 + tx;
        float x = e.src[(size_t)k * e.N + n];
        __nv_bfloat16 h = __float2bfloat16_rn(x);
        __nv_bfloat16 l = __float2bfloat16_rn(x - __bfloat162float(h));
        sh[ty + 8 * i][tx] = (uint32_t)(*(unsigned short*)&h);
        sl[ty + 8 * i][tx] = (uint32_t)(*(unsigned short*)&l);
    }
    __syncthreads();

#pragma unroll
    for (int i = 0; i < 4; i++) {
        int n = tn0 + ty + 8 * i;
        int k = tk0 + tx;
        unsigned short hv = (unsigned short)sh[tx][ty + 8 * i];
        unsigned short lv = (unsigned short)sl[tx][ty + 8 * i];
        size_t di = (size_t)n * e.K + k;
        *(unsigned short*)&e.hi[di] = hv;
        *(unsigned short*)&e.lo[di] = lv;
    }
}

// ================= pipelined tensor-core GEMM (R11 config + fused gate) ======
#define SA   40
#define BUFE (128 * SA)
#define SMEM_GEMM (8 * BUFE * 2)

__device__ __forceinline__ void mma_bf16(float* c, const uint32_t* a,
                                         uint32_t b0, uint32_t b1)
{
    asm volatile(
        "mma.sync.aligned.m16n8k16.row.col.f32.bf16.bf16.f32 "
        "{%0,%1,%2,%3}, {%4,%5,%6,%7}, {%8,%9}, {%0,%1,%2,%3};\n"
        : "+f"(c[0]), "+f"(c[1]), "+f"(c[2]), "+f"(c[3])
        : "r"(a[0]), "r"(a[1]), "r"(a[2]), "r"(a[3]), "r"(b0), "r"(b1));
}

__device__ __forceinline__ void cp16(void* s, const void* g)
{
    uint32_t sa = (uint32_t)__cvta_generic_to_shared(s);
    asm volatile("cp.async.ca.shared.global [%0], [%1], 16;\n" :: "r"(sa), "l"(g));
}

__device__ __forceinline__ void ldmat4(uint32_t& r0, uint32_t& r1,
                                       uint32_t& r2, uint32_t& r3, uint32_t addr)
{
    asm volatile("ldmatrix.sync.aligned.m8n8.x4.shared.b16 {%0,%1,%2,%3}, [%4];\n"
                 : "=r"(r0), "=r"(r1), "=r"(r2), "=r"(r3) : "r"(addr));
}

__global__ __launch_bounds__(256, 2) void gemm_tc(
    const __nv_bfloat16* __restrict__ Ah, const __nv_bfloat16* __restrict__ Al,
    const __nv_bfloat16* __restrict__ Bh, const __nv_bfloat16* __restrict__ Bl,
    const float* __restrict__ bias,
    float* __restrict__ Cf,
    __nv_bfloat16* __restrict__ Chi, __nv_bfloat16* __restrict__ Clo,
    const float* __restrict__ gvw, float* __restrict__ gso,
    int M, int K, int Nout, int act)
{
    extern __shared__ __nv_bfloat16 sm[];
    __nv_bfloat16* sAh = sm;
    __nv_bfloat16* sAl = sm + 2 * BUFE;
    __nv_bfloat16* sBh = sm + 4 * BUFE;
    __nv_bfloat16* sBl = sm + 6 * BUFE;

    const int t = threadIdx.x;
    const int warp = t >> 5, lane = t & 31;
    const int wm = (warp & 1) * 64;
    const int wn = (warp >> 1) * 32;
    const int r = lane >> 2, c2 = (lane & 3) * 2;
    const int m0 = blockIdx.y * 128;
    const int n0 = blockIdx.x * 128;

    const int lr = t >> 2;
    const int lc = (t & 3) * 8;

    const int g8 = lane >> 3;
    const int lrow = (g8 & 1) * 8 + (lane & 7);
    const int kof = (g8 >> 1) * 8;

    float acc[4][4][4];
#pragma unroll
    for (int i = 0; i < 4; i++)
#pragma unroll
        for (int j = 0; j < 4; j++)
#pragma unroll
            for (int k = 0; k < 4; k++) acc[i][j][k] = 0.f;

    const __nv_bfloat16* pAh = Ah + (size_t)(m0 + lr) * K + lc;
    const __nv_bfloat16* pAl = Al + (size_t)(m0 + lr) * K + lc;
    const __nv_bfloat16* pBh = Bh + (size_t)(n0 + lr) * K + lc;
    const __nv_bfloat16* pBl = Bl + (size_t)(n0 + lr) * K + lc;
    const size_t rs64 = (size_t)64 * K;

    const int so0 = lr * SA + lc;
    const int so1 = (lr + 64) * SA + lc;

    uint32_t bAh = (uint32_t)__cvta_generic_to_shared(sAh);
    uint32_t bAl = (uint32_t)__cvta_generic_to_shared(sAl);
    uint32_t bBh = (uint32_t)__cvta_generic_to_shared(sBh);
    uint32_t bBl = (uint32_t)__cvta_generic_to_shared(sBl);

    uint32_t aoff[4], boff[2];
#pragma unroll
    for (int mt = 0; mt < 4; mt++)
        aoff[mt] = ((wm + mt * 16 + lrow) * SA + kof) * 2;
#pragma unroll
    for (int ntp = 0; ntp < 2; ntp++)
        boff[ntp] = ((wn + ntp * 16 + lrow) * SA + kof) * 2;

    cp16(&sAh[so0], pAh);            cp16(&sAh[so1], pAh + rs64);
    cp16(&sAl[so0], pAl);            cp16(&sAl[so1], pAl + rs64);
    cp16(&sBh[so0], pBh);            cp16(&sBh[so1], pBh + rs64);
    cp16(&sBl[so0], pBl);            cp16(&sBl[so1], pBl + rs64);
    asm volatile("cp.async.commit_group;\n");

    const int nIter = K >> 5;
    for (int i = 0; i < nIter; i++) {
        const int s = i & 1;
        if (i + 1 < nIter) {
            int k0 = (i + 1) << 5;
            int nso = ((i + 1) & 1) * BUFE;
            cp16(&sAh[nso + so0], pAh + k0);  cp16(&sAh[nso + so1], pAh + rs64 + k0);
            cp16(&sAl[nso + so0], pAl + k0);  cp16(&sAl[nso + so1], pAl + rs64 + k0);
            cp16(&sBh[nso + so0], pBh + k0);  cp16(&sBh[nso + so1], pBh + rs64 + k0);
            cp16(&sBl[nso + so0], pBl + k0);  cp16(&sBl[nso + so1], pBl + rs64 + k0);
            asm volatile("cp.async.commit_group;\n");
            asm volatile("cp.async.wait_group 1;\n");
        } else {
            asm volatile("cp.async.wait_group 0;\n");
        }
        __syncthreads();

        const uint32_t sb = s * BUFE * 2;
#pragma unroll
        for (int ks = 0; ks < 2; ks++) {
            const uint32_t kso = sb + ks * 32;
            uint32_t ah[4][4], al[4][4];
#pragma unroll
            for (int mt = 0; mt < 4; mt++) {
                ldmat4(ah[mt][0], ah[mt][1], ah[mt][2], ah[mt][3], bAh + kso + aoff[mt]);
                ldmat4(al[mt][0], al[mt][1], al[mt][2], al[mt][3], bAl + kso + aoff[mt]);
            }
#pragma unroll
            for (int ntp = 0; ntp < 2; ntp++) {
                uint32_t h0, h1, h2, h3, l0, l1, l2, l3;
                ldmat4(h0, h1, h2, h3, bBh + kso + boff[ntp]);
                ldmat4(l0, l1, l2, l3, bBl + kso + boff[ntp]);
#pragma unroll
                for (int mt = 0; mt < 4; mt++) {
                    mma_bf16(acc[mt][2 * ntp],     ah[mt], h0, h2);
                    mma_bf16(acc[mt][2 * ntp],     al[mt], h0, h2);
                    mma_bf16(acc[mt][2 * ntp],     ah[mt], l0, l2);
                    mma_bf16(acc[mt][2 * ntp + 1], ah[mt], h1, h3);
                    mma_bf16(acc[mt][2 * ntp + 1], al[mt], h1, h3);
                    mma_bf16(acc[mt][2 * ntp + 1], ah[mt], l1, l3);
                }
            }
        }
        __syncthreads();
    }

    // epilogue (+ optional fused gating row-dot)
    float rowacc[4][2];
#pragma unroll
    for (int i = 0; i < 4; i++) { rowacc[i][0] = 0.f; rowacc[i][1] = 0.f; }

#pragma unroll
    for (int nt = 0; nt < 4; nt++) {
        int col = n0 + wn + nt * 8 + c2;
        float b0 = bias ? bias[col] : 0.f;
        float b1 = bias ? bias[col + 1] : 0.f;
        float w0 = gvw ? gvw[col] : 0.f;
        float w1 = gvw ? gvw[col + 1] : 0.f;
#pragma unroll
        for (int mt = 0; mt < 4; mt++) {
            int row = m0 + wm + mt * 16 + r;
#pragma unroll
            for (int half = 0; half < 2; half++) {
                int rr = row + half * 8;
                float v0 = acc[mt][nt][half * 2 + 0] + b0;
                float v1 = acc[mt][nt][half * 2 + 1] + b1;
                if (act == 1) { v0 = fmaxf(v0, 0.f); v1 = fmaxf(v1, 0.f); }
                else if (act == 2) {
                    v0 = 0.5f * v0 * (1.f + erff(v0 * 0.70710678118654752f));
                    v1 = 0.5f * v1 * (1.f + erff(v1 * 0.70710678118654752f));
                }
                if (gvw) rowacc[mt][half] += v0 * w0 + v1 * w1;
                size_t o = (size_t)rr * Nout + col;
                if (Cf) *(float2*)(Cf + o) = make_float2(v0, v1);
                if (Chi) {
                    __nv_bfloat16 h0 = __float2bfloat16_rn(v0);
                    __nv_bfloat16 h1 = __float2bfloat16_rn(v1);
                    __nv_bfloat162 hp; hp.x = h0; hp.y = h1;
                    *(__nv_bfloat162*)(Chi + o) = hp;
                    __nv_bfloat162 lp;
                    lp.x = __float2bfloat16_rn(v0 - __bfloat162float(h0));
                    lp.y = __float2bfloat16_rn(v1 - __bfloat162float(h1));
                    *(__nv_bfloat162*)(Clo + o) = lp;
                }
            }
        }
    }
    if (gvw) {
#pragma unroll
        for (int mt = 0; mt < 4; mt++)
#pragma unroll
            for (int half = 0; half < 2; half++) {
                float v = rowacc[mt][half];
                v += __shfl_xor_sync(0xffffffffu, v, 1);
                v += __shfl_xor_sync(0xffffffffu, v, 2);
                if ((lane & 3) == 0) {
                    int row = m0 + wm + mt * 16 + r + half * 8;
                    atomicAdd(gso + row, v);
                }
            }
    }
}

// ---------------- fold edge projection into per-layer 32-dim vector ----------------
__global__ void wa_kernel(const float* __restrict__ We, const float* __restrict__ be,
                          const float* __restrict__ gat_a)
{
    int l = blockIdx.x;
    int t = threadIdx.x;
    const float* a = gat_a + l * (3 * HH) + 2 * HH;
    if (t < 32) {
        float s = 0.f;
        const float* row = We + t * HH;
        for (int j = 0; j < HH; j++) s += row[j] * a[j];
        g_wa[l * 32 + t] = s;
    } else if (t == 32) {
        float s = 0.f;
        for (int j = 0; j < HH; j++) s += be[j] * a[j];
        g_cb[l] = s;
    }
}

// ---------------- per-edge ce for ALL layers ----------------
__global__ __launch_bounds__(256) void ce_kernel(const float* __restrict__ ef)
{
    int e = blockIdx.x * 256 + threadIdx.x;
    float4 v[8];
    const float4* row = (const float4*)(ef + (size_t)e * 32);
#pragma unroll
    for (int i = 0; i < 8; i++) v[i] = row[i];
#pragma unroll
    for (int l = 0; l < LL; l++) {
        const float* wa = g_wa + l * 32;
        float s = g_cb[l];
#pragma unroll
        for (int i = 0; i < 8; i++) {
            s += v[i].x * wa[4 * i + 0];
            s += v[i].y * wa[4 * i + 1];
            s += v[i].z * wa[4 * i + 2];
            s += v[i].w * wa[4 * i + 3];
        }
        g_ce[l * EE + e] = s;
    }
}

// ---------------- graph-resident GAT layer (512 threads, cp.async tile load) ----
#define GATSM (NPG * HH * 4 + (64 + 64 + 512) * 4 + 512 * 4)

__global__ __launch_bounds__(512) void gat_layer_kernel(
    const int* __restrict__ dst, const float* __restrict__ ce_l,
    const float* __restrict__ gat_a,
    const float* __restrict__ lng, const float* __restrict__ lnb, int l)
{
    extern __shared__ float smf[];
    float* smm = smf;
    float* sas = smf + NPG * HH;
    float* sad = sas + 64;
    float* swt = sad + 64;
    int*   sdl = (int*)(swt + 512);

    const int g = blockIdx.x;
    const int t = threadIdx.x;
    const int warp = t >> 5, lane = t & 31;

    // load the graph's 64KB m tile via cp.async (no register staging)
    {
        const float* src = g_m + (size_t)g * NPG * HH;
#pragma unroll
        for (int i = 0; i < 8; i++)
            cp16(&smm[(t + 512 * i) * 4], src + (t + 512 * i) * 4);
        asm volatile("cp.async.commit_group;\n");
        asm volatile("cp.async.wait_group 0;\n");
    }
    __syncthreads();

    {
        const float* a1 = gat_a + l * (3 * HH);
        const float* a2 = a1 + HH;
#pragma unroll
        for (int q = 0; q < 4; q++) {
            int i = warp * 4 + q;
            const float* mr = smm + i * HH;
            float s = 0.f, d = 0.f;
#pragma unroll
            for (int j = lane; j < HH; j += 32) {
                float mv = mr[j];
                s += mv * a1[j];
                d += mv * a2[j];
            }
#pragma unroll
            for (int off = 16; off; off >>= 1) {
                s += __shfl_xor_sync(0xffffffffu, s, off);
                d += __shfl_xor_sync(0xffffffffu, d, off);
            }
            if (lane == 0) { sas[i] = s; sad[i] = d; }
        }
    }
    __syncthreads();

    if (t < NPG) {
        float lg[DEG];
        int   dl[DEG];
#pragma unroll
        for (int k = 0; k < DEG; k++) {
            int e = t * DEG + k;
            int d = dst[g * (NPG * DEG) + e] - g * NPG;
            dl[k] = d;
            float x = sas[t] + sad[d] + ce_l[g * (NPG * DEG) + e];
            lg[k] = (x >= 0.f) ? x : 0.01f * x;
        }
        float mx = -1e30f;
#pragma unroll
        for (int k = 0; k < DEG; k++) mx = fmaxf(mx, lg[k]);
        float ws = 0.f;
#pragma unroll
        for (int k = 0; k < DEG; k++) { lg[k] = __expf(lg[k] - mx); ws += lg[k]; }
        float inv = 1.f / ws;
#pragma unroll
        for (int k = 0; k < DEG; k++) {
            swt[t * DEG + k] = lg[k] * inv;
            sdl[t * DEG + k] = dl[k];
        }
    }
    __syncthreads();

#pragma unroll
    for (int q = 0; q < 4; q++) {
        int i = warp * 4 + q;
        float acc[8] = {0.f, 0.f, 0.f, 0.f, 0.f, 0.f, 0.f, 0.f};
#pragma unroll
        for (int k = 0; k < DEG; k++) {
            float wk = swt[i * DEG + k];
            const float4* mr = (const float4*)(smm + sdl[i * DEG + k] * HH) + lane * 2;
            float4 v0 = mr[0], v1 = mr[1];
            acc[0] += wk * v0.x; acc[1] += wk * v0.y;
            acc[2] += wk * v0.z; acc[3] += wk * v0.w;
            acc[4] += wk * v1.x; acc[5] += wk * v1.y;
            acc[6] += wk * v1.z; acc[7] += wk * v1.w;
        }
        size_t rowo = (size_t)(g * NPG + i) * HH + lane * 8;
        const float4* hr = (const float4*)(g_h + rowo);
        float4 h0 = hr[0], h1 = hr[1];
        float x[8];
        x[0] = acc[0] + h0.x; x[1] = acc[1] + h0.y;
        x[2] = acc[2] + h0.z; x[3] = acc[3] + h0.w;
        x[4] = acc[4] + h1.x; x[5] = acc[5] + h1.y;
        x[6] = acc[6] + h1.z; x[7] = acc[7] + h1.w;

        float s = 0.f, s2 = 0.f;
#pragma unroll
        for (int c = 0; c < 8; c++) { s += x[c]; s2 += x[c] * x[c]; }
#pragma unroll
        for (int off = 16; off; off >>= 1) {
            s  += __shfl_xor_sync(0xffffffffu, s,  off);
            s2 += __shfl_xor_sync(0xffffffffu, s2, off);
        }
        float mean = s * (1.f / HH);
        float var  = s2 * (1.f / HH) - mean * mean;
        float rstd = rsqrtf(var + 1e-5f);

        const float4* gg = (const float4*)(lng + l * HH + lane * 8);
        const float4* bb = (const float4*)(lnb + l * HH + lane * 8);
        float4 gv0 = gg[0], gv1 = gg[1];
        float4 bv0 = bb[0], bv1 = bb[1];
        float y[8];
        y[0] = (x[0] - mean) * rstd * gv0.x + bv0.x;
        y[1] = (x[1] - mean) * rstd * gv0.y + bv0.y;
        y[2] = (x[2] - mean) * rstd * gv0.z + bv0.z;
        y[3] = (x[3] - mean) * rstd * gv0.w + bv0.w;
        y[4] = (x[4] - mean) * rstd * gv1.x + bv1.x;
        y[5] = (x[5] - mean) * rstd * gv1.y + bv1.y;
        y[6] = (x[6] - mean) * rstd * gv1.z + bv1.z;
        y[7] = (x[7] - mean) * rstd * gv1.w + bv1.w;

        float4* ho = (float4*)(g_h + rowo);
        ho[0] = make_float4(y[0], y[1], y[2], y[3]);
        ho[1] = make_float4(y[4], y[5], y[6], y[7]);

        uint32_t hi[4], lo[4];
#pragma unroll
        for (int c = 0; c < 4; c++) {
            __nv_bfloat16 a0 = __float2bfloat16_rn(y[2 * c]);
            __nv_bfloat16 a1 = __float2bfloat16_rn(y[2 * c + 1]);
            __nv_bfloat162 hp; hp.x = a0; hp.y = a1;
            hi[c] = *(uint32_t*)&hp;
            __nv_bfloat162 lp;
            lp.x = __float2bfloat16_rn(y[2 * c] - __bfloat162float(a0));
            lp.y = __float2bfloat16_rn(y[2 * c + 1] - __bfloat162float(a1));
            lo[c] = *(uint32_t*)&lp;
        }
        *(uint4*)(g_h_h + rowo) = make_uint4(hi[0], hi[1], hi[2], hi[3]);
        *(uint4*)(g_h_l + rowo) = make_uint4(lo[0], lo[1], lo[2], lo[3]);
    }
}

// ---------------- residual + LayerNorm (+ optional bf16 hi/lo out) ----------------
__global__ __launch_bounds__(256) void ln_kernel(
    const float* __restrict__ xa, const float* __restrict__ xb,
    const float* __restrict__ g, const float* __restrict__ b,
    float* __restrict__ out,
    __nv_bfloat16* __restrict__ ohi, __nv_bfloat16* __restrict__ olo,
    float eps)
{
    __shared__ float rs[8], rs2[8];
    int n = blockIdx.x;
    int t = threadIdx.x;
    int warp = t >> 5, lane = t & 31;
    float x = xa[(size_t)n * HH + t] + xb[(size_t)n * HH + t];
    float s = x, s2 = x * x;
#pragma unroll
    for (int off = 16; off; off >>= 1) {
        s  += __shfl_xor_sync(0xffffffffu, s,  off);
        s2 += __shfl_xor_sync(0xffffffffu, s2, off);
    }
    if (lane == 0) { rs[warp] = s; rs2[warp] = s2; }
    __syncthreads();
    if (warp == 0) {
        float a = (lane < 8) ? rs[lane]  : 0.f;
        float c = (lane < 8) ? rs2[lane] : 0.f;
#pragma unroll
        for (int off = 4; off; off >>= 1) {
            a += __shfl_xor_sync(0xffffffffu, a, off);
            c += __shfl_xor_sync(0xffffffffu, c, off);
        }
        if (lane == 0) { rs[0] = a; rs2[0] = c; }
    }
    __syncthreads();
    float mean = rs[0] * (1.f / HH);
    float var  = rs2[0] * (1.f / HH) - mean * mean;
    float y = (x - mean) * rsqrtf(var + eps) * g[t] + b[t];
    size_t o = (size_t)n * HH + t;
    out[o] = y;
    if (ohi) {
        __nv_bfloat16 hh = __float2bfloat16_rn(y);
        ohi[o] = hh;
        olo[o] = __float2bfloat16_rn(y - __bfloat162float(hh));
    }
}

// ---------------- per-(graph, head) global attention (packed qkv) ----------------
__global__ __launch_bounds__(256) void attn_kernel()
{
    __shared__ float qs[NPG][33];
    __shared__ float ks[NPG][33];
    __shared__ float vs[NPG][DKH];
    __shared__ float pb[8][NPG];

    int head = blockIdx.x;
    int b = blockIdx.y;
    int t = threadIdx.x;
    int warp = t >> 5, lane = t & 31;

    for (int idx = t; idx < NPG * DKH; idx += 256) {
        int r = idx >> 5, d = idx & 31;
        size_t g = (size_t)(b * NPG + r) * 768 + head * DKH + d;
        qs[r][d] = g_qkv[g];
        ks[r][d] = g_qkv[g + 256];
        vs[r][d] = g_qkv[g + 512];
    }
    __syncthreads();

    const float scale = 0.17677669529663687f;
    for (int r = 0; r < 8; r++) {
        int i = warp * 8 + r;
        float s0 = 0.f, s1 = 0.f;
#pragma unroll
        for (int d = 0; d < DKH; d++) {
            float qd = qs[i][d];
            s0 += qd * ks[lane][d];
            s1 += qd * ks[lane + 32][d];
        }
        s0 *= scale; s1 *= scale;
        float mx = fmaxf(s0, s1);
#pragma unroll
        for (int off = 16; off; off >>= 1)
            mx = fmaxf(mx, __shfl_xor_sync(0xffffffffu, mx, off));
        float e0 = __expf(s0 - mx), e1 = __expf(s1 - mx);
        float sm = e0 + e1;
#pragma unroll
        for (int off = 16; off; off >>= 1)
            sm += __shfl_xor_sync(0xffffffffu, sm, off);
        float inv = 1.f / sm;
        pb[warp][lane] = e0 * inv;
        pb[warp][lane + 32] = e1 * inv;
        __syncwarp();
        float o = 0.f;
#pragma unroll
        for (int j = 0; j < NPG; j++) o += pb[warp][j] * vs[j][lane];
        g_o[(size_t)(b * NPG + i) * HH + head * DKH + lane] = o;
    }
}

// ---------------- gated readout per graph ----------------
__global__ __launch_bounds__(256) void readout_kernel(float* __restrict__ out)
{
    __shared__ float p[NPG];
    int b = blockIdx.x;
    int t = threadIdx.x;
    if (t < NPG) p[t] = g_gs[b * NPG + t];
    __syncthreads();
    float mx = -1e30f;
#pragma unroll
    for (int i = 0; i < NPG; i++) mx = fmaxf(mx, p[i]);
    float s = 0.f, acc = 0.f;
    for (int i = 0; i < NPG; i++) {
        float w = __expf(p[i] - mx);
        s += w;
        acc += w * g_h[(size_t)(b * NPG + i) * HH + t];
    }
    out[b * HH + t] = acc / s;
}

// ---------------- host launcher ----------------
static inline __nv_bfloat16* sym(const void* s)
{
    void* p = nullptr;
    cudaGetSymbolAddress(&p, s);
    return (__nv_bfloat16*)p;
}

extern "C" void kernel_launch(void* const* d_in, const int* in_sizes, int n_in,
                              void* d_out, int out_size)
{
    const float* node_feats = (const float*)d_in[0];
    const float* edge_feats = (const float*)d_in[1];
    const int*   dst        = (const int*)  d_in[3];
    const float* Wn   = (const float*)d_in[4];
    const float* bn   = (const float*)d_in[5];
    const float* We   = (const float*)d_in[6];
    const float* be   = (const float*)d_in[7];
    const float* gatW = (const float*)d_in[8];
    const float* gata = (const float*)d_in[9];
    const float* glng = (const float*)d_in[10];
    const float* glnb = (const float*)d_in[11];
    const float* Wq   = (const float*)d_in[12];
    const float* Wk   = (const float*)d_in[13];
    const float* Wv   = (const float*)d_in[14];
    const float* alng = (const float*)d_in[15];
    const float* alnb = (const float*)d_in[16];
    const float* fW1  = (const float*)d_in[17];
    const float* fb1  = (const float*)d_in[18];
    const float* fW2  = (const float*)d_in[19];
    const float* fb2  = (const float*)d_in[20];
    const float* flng = (const float*)d_in[21];
    const float* flnb = (const float*)d_in[22];
    const float* gW1  = (const float*)d_in[23];
    const float* gb1  = (const float*)d_in[24];
    const float* gW2  = (const float*)d_in[25];
    float* out = (float*)d_out;

    cudaFuncSetAttribute(gemm_tc, cudaFuncAttributeMaxDynamicSharedMemorySize,
                         SMEM_GEMM);
    cudaFuncSetAttribute(gat_layer_kernel,
                         cudaFuncAttributeMaxDynamicSharedMemorySize, GATSM);

    float *h_p, *m_p, *qkv_p, *o_p, *ce_p, *gs_p;
    cudaGetSymbolAddress((void**)&h_p, g_h);
    cudaGetSymbolAddress((void**)&m_p, g_m);
    cudaGetSymbolAddress((void**)&qkv_p, g_qkv);
    cudaGetSymbolAddress((void**)&o_p, g_o);
    cudaGetSymbolAddress((void**)&ce_p, g_ce);
    cudaGetSymbolAddress((void**)&gs_p, g_gs);

    __nv_bfloat16 *nf_h = sym(g_nf_h), *nf_l = sym(g_nf_l);
    __nv_bfloat16 *h_h = sym(g_h_h),  *h_l = sym(g_h_l);
    __nv_bfloat16 *ff_h = sym(g_ff_h), *ff_l = sym(g_ff_l);
    __nv_bfloat16 *wnt_h = sym(g_wnt_h), *wnt_l = sym(g_wnt_l);
    __nv_bfloat16 *gwt_h = sym(g_gatwt_h), *gwt_l = sym(g_gatwt_l);
    __nv_bfloat16 *qkvt_h = sym(g_qkvt_h), *qkvt_l = sym(g_qkvt_l);
    __nv_bfloat16 *f1t_h = sym(g_ff1t_h), *f1t_l = sym(g_ff1t_l);
    __nv_bfloat16 *f2t_h = sym(g_ff2t_h), *f2t_l = sym(g_ff2t_l);
    __nv_bfloat16 *g1t_h = sym(g_gw1t_h), *g1t_l = sym(g_gw1t_l);

    ConvTab tab;
    int ne = 0, blk = 0;
    auto add = [&](const float* s, __nv_bfloat16* hi, __nv_bfloat16* lo,
                   int K, int N, int tr) {
        int nb = (K * N + 1023) / 1024;
        tab.e[ne] = {s, hi, lo, K, N, tr, blk, nb};
        blk += nb; ne++;
    };
    add(Wn, wnt_h, wnt_l, 64, HH, 1);
    for (int l = 0; l < LL; l++)
        add(gatW + (size_t)l * HH * HH, gwt_h + (size_t)l * HH * HH,
            gwt_l + (size_t)l * HH * HH, HH, HH, 1);
    add(Wq, qkvt_h, qkvt_l, HH, HH, 1);
    add(Wk, qkvt_h + 256 * HH, qkvt_l + 256 * HH, HH, HH, 1);
    add(Wv, qkvt_h + 512 * HH, qkvt_l + 512 * HH, HH, HH, 1);
    add(fW1, f1t_h, f1t_l, HH, FFD, 1);
    add(fW2, f2t_h, f2t_l, FFD, HH, 1);
    add(gW1, g1t_h, g1t_l, HH, HH, 1);
    add(node_feats, nf_h, nf_l, NN, 64, 0);
    tab.n = ne;

    conv_kernel<<<blk, 256>>>(tab);
    wa_kernel<<<LL, 64>>>(We, be, gata);
    ce_kernel<<<EE / 256, 256>>>(edge_feats);
    cudaMemsetAsync(gs_p, 0, NN * sizeof(float));

    dim3 gH(HH / 128, NN / 128);     // (2, 128)
    dim3 gQKV(768 / 128, NN / 128);  // (6, 128)
    dim3 gF(FFD / 128, NN / 128);    // (4, 128)

    gemm_tc<<<gH, 256, SMEM_GEMM>>>(nf_h, nf_l, wnt_h, wnt_l, bn, h_p, h_h, h_l,
                                    nullptr, nullptr, NN, 64, HH, 0);

    for (int l = 0; l < LL; l++) {
        gemm_tc<<<gH, 256, SMEM_GEMM>>>(h_h, h_l, gwt_h + (size_t)l * HH * HH,
                                        gwt_l + (size_t)l * HH * HH, nullptr,
                                        m_p, nullptr, nullptr,
                                        nullptr, nullptr, NN, HH, HH, 0);
        gat_layer_kernel<<<GB, 512, GATSM>>>(dst, ce_p + (size_t)l * EE,
                                             gata, glng, glnb, l);
    }

    gemm_tc<<<gQKV, 256, SMEM_GEMM>>>(h_h, h_l, qkvt_h, qkvt_l, nullptr, qkv_p,
                                      nullptr, nullptr, nullptr, nullptr,
                                      NN, HH, 768, 0);
    attn_kernel<<<dim3(NHEADS, GB), 256>>>();
    ln_kernel<<<NN, 256>>>(o_p, h_p, alng, alnb, h_p, h_h, h_l, 1e-6f);

    gemm_tc<<<gF, 256, SMEM_GEMM>>>(h_h, h_l, f1t_h, f1t_l, fb1, nullptr,
                                    ff_h, ff_l, nullptr, nullptr,
                                    NN, HH, FFD, 2);
    gemm_tc<<<gH, 256, SMEM_GEMM>>>(ff_h, ff_l, f2t_h, f2t_l, fb2, m_p,
                                    nullptr, nullptr, nullptr, nullptr,
                                    NN, FFD, HH, 0);
    ln_kernel<<<NN, 256>>>(h_p, m_p, flng, flnb, h_p, h_h, h_l, 1e-6f);

    // gating: relu(x@gW1+gb1) fused with dot(gW2) into g_gs (atomic epilogue)
    gemm_tc<<<gH, 256, SMEM_GEMM>>>(h_h, h_l, g1t_h, g1t_l, gb1, nullptr,
                                    nullptr, nullptr, gW2, gs_p,
                                    NN, HH, HH, 1);
    readout_kernel<<<GB, 256>>>(out);

    (void)in_sizes; (void)n_in; (void)out_size;
}